// round 1
// baseline (speedup 1.0000x reference)
#include <cuda_runtime.h>

#define BB 16
#define LL 24
#define NN 256
#define EE 4096
#define HH 64
#define G4 256          // 4*H
#define TT (BB*LL)      // 384 graphs
#define BN (BB*NN)      // 4096 LSTM samples
#define S_LSTM 16       // samples per LSTM block

// ---------------- device scratch (no allocation allowed) ----------------
__device__ float g_Hout[TT * NN * HH];     // [t][n][64]  (25 MB)
__device__ float g_M1[64 * 64];            // W1a @ W2b
__device__ float g_M2[64 * 64];            // W1b @ W2b
__device__ float g_Cp[NN * 64];            // per-node constant term (already @W2b)
__device__ float g_G0[64], g_G1[64], g_Gb[64];
__device__ int   g_deg[NN];
__device__ int   g_off[NN + 1];
__device__ int   g_src[EE];

// ---------------- setup: CSR, degrees, folded weight products ----------------
__global__ void setup_kernel(const int* __restrict__ conn,
                             const float* __restrict__ city_w,
                             const float* __restrict__ W1,   // [130,64]
                             const float* __restrict__ b1,   // [64]
                             const float* __restrict__ W2)   // [128,64]
{
    __shared__ float s0[NN], s1[NN];
    __shared__ int degs[NN], cur[NN];
    int t = threadIdx.x;

    s0[t] = 0.f; s1[t] = 0.f; degs[t] = 0;
    __syncthreads();

    const int* row = conn;
    const int* col = conn + EE;
    for (int e = t; e < EE; e += 256) {
        int c = col[e];
        atomicAdd(&degs[c], 1);
        atomicAdd(&s0[c], city_w[2 * e + 0]);
        atomicAdd(&s1[c], city_w[2 * e + 1]);
    }
    __syncthreads();

    if (t == 0) {
        int acc = 0;
        for (int n = 0; n < NN; n++) { g_off[n] = acc; acc += degs[n]; }
        g_off[NN] = acc;
    }
    __syncthreads();
    cur[t] = g_off[t];
    g_deg[t] = degs[t];
    __syncthreads();
    for (int e = t; e < EE; e += 256) {
        int c = col[e];
        int p = atomicAdd(&cur[c], 1);
        g_src[p] = row[e];
    }

    // M1[k][c] = sum_j W1a[k][j]*W2b[j][c],  M2 same with W1b
    for (int idx = t; idx < 64 * 64; idx += 256) {
        int k = idx >> 6, c = idx & 63;
        float a1 = 0.f, a2 = 0.f;
        for (int j = 0; j < 64; j++) {
            float w2 = W2[(64 + j) * 64 + c];
            a1 += W1[k * 64 + j] * w2;
            a2 += W1[(64 + k) * 64 + j] * w2;
        }
        g_M1[idx] = a1; g_M2[idx] = a2;
    }
    // G0 = W1c_row0 @ W2b, G1 = W1c_row1 @ W2b, Gb = b1 @ W2b
    if (t < 64) {
        float a0 = 0.f, a1 = 0.f, ab = 0.f;
        for (int k = 0; k < 64; k++) {
            float w2 = W2[(64 + k) * 64 + t];
            a0 += W1[128 * 64 + k] * w2;
            a1 += W1[129 * 64 + k] * w2;
            ab += b1[k] * w2;
        }
        g_G0[t] = a0; g_G1[t] = a1; g_Gb[t] = ab;
    }
    __syncthreads();
    // Cp[n][c] = s0[n]*G0[c] + s1[n]*G1[c] + deg[n]*Gb[c]
    for (int idx = t; idx < NN * 64; idx += 256) {
        int n = idx >> 6, c = idx & 63;
        g_Cp[idx] = s0[n] * g_G0[c] + s1[n] * g_G1[c] + (float)degs[n] * g_Gb[c];
    }
}

// ---------------- LSTM (persistent over 24 steps, parallel over samples) -------
__device__ __forceinline__ float fsig(float x) { return 1.f / (1.f + __expf(-x)); }
__device__ __forceinline__ float ftanh(float x) {
    float e = __expf(2.f * fabsf(x));
    float t = 1.f - 2.f / (e + 1.f);
    return copysignf(t, x);
}

__global__ void __launch_bounds__(256, 2)
lstm_kernel(const float* __restrict__ aqi,   // [B,24,N,1]
            const float* __restrict__ embW,  // [1,16]
            const float* __restrict__ embB,  // [16]
            const float* __restrict__ Wih,   // [256,16]
            const float* __restrict__ Whh,   // [256,64]
            const float* __restrict__ bih,   // [256]
            const float* __restrict__ bhh)   // [256]
{
    __shared__ float hS[S_LSTM][64];
    __shared__ float cS[S_LSTM][64];
    __shared__ float gS[S_LSTM][256];
    __shared__ float aS[S_LSTM][LL];

    int tid = threadIdx.x;         // gate row r in [0,256)
    int m0  = blockIdx.x * S_LSTM; // first sample of this block

    // W_hh row r in registers
    float w[64];
    {
        const float4* wr = (const float4*)(Whh + tid * 64);
#pragma unroll
        for (int i = 0; i < 16; i++) {
            float4 v = wr[i];
            w[4*i] = v.x; w[4*i+1] = v.y; w[4*i+2] = v.z; w[4*i+3] = v.w;
        }
    }
    // fold embedding + input projection: xg[r] = aqi*A + Bc
    float A = 0.f, Bc = 0.f;
#pragma unroll
    for (int j = 0; j < 16; j++) {
        float wi = Wih[tid * 16 + j];
        A  += wi * embW[j];
        Bc += wi * embB[j];
    }
    Bc += bih[tid] + bhh[tid];

    for (int idx = tid; idx < S_LSTM * LL; idx += 256) {
        int s = idx / LL, l = idx % LL;
        int m = m0 + s; int b = m >> 8; int n = m & 255;
        aS[s][l] = aqi[(b * LL + l) * NN + n];
    }
    for (int idx = tid; idx < S_LSTM * 64; idx += 256) {
        ((float*)hS)[idx] = 0.f; ((float*)cS)[idx] = 0.f;
    }
    __syncthreads();

    for (int l = 0; l < LL; l++) {
        // gates[s][r] = aqi*A + Bc + sum_k h[s][k]*w[k]
#pragma unroll 2
        for (int s = 0; s < S_LSTM; s++) {
            float a0 = 0.f, a1 = 0.f, a2 = 0.f, a3 = 0.f;
            const float4* hp = (const float4*)hS[s];
#pragma unroll
            for (int i = 0; i < 16; i++) {
                float4 hv = hp[i];
                a0 += hv.x * w[4*i];
                a1 += hv.y * w[4*i+1];
                a2 += hv.z * w[4*i+2];
                a3 += hv.w * w[4*i+3];
            }
            gS[s][tid] = aS[s][l] * A + Bc + ((a0 + a1) + (a2 + a3));
        }
        __syncthreads();
        // cell update + write h to global
#pragma unroll
        for (int u = 0; u < (S_LSTM * 64) / 256; u++) {
            int idx = u * 256 + tid;
            int s = idx >> 6, j = idx & 63;
            float gi = gS[s][j];
            float gf = gS[s][64 + j];
            float gg = gS[s][128 + j];
            float go = gS[s][192 + j];
            float cn = fsig(gf) * cS[s][j] + fsig(gi) * ftanh(gg);
            float hn = fsig(go) * ftanh(cn);
            cS[s][j] = cn; hS[s][j] = hn;
            int m = m0 + s; int b = m >> 8; int n = m & 255;
            g_Hout[(((b * LL + l) * NN) + n) * 64 + j] = hn;
        }
        __syncthreads();
    }
}

// ---------------- GNN: one block per graph t ----------------
#define GNN_SMEM_FLOATS (4096 + 3 * 256 * 65)
#define GNN_SMEM_BYTES  (GNN_SMEM_FLOATS * 4)

__device__ __forceinline__ void gemv64(const float* __restrict__ xrow,
                                       const float* __restrict__ Wb,
                                       float* acc)
{
#pragma unroll
    for (int c = 0; c < 64; c++) acc[c] = 0.f;
#pragma unroll 2
    for (int k = 0; k < 64; k++) {
        float xv = xrow[k];
        const float4* wr = (const float4*)(Wb + (k << 6));
#pragma unroll
        for (int i = 0; i < 16; i++) {
            float4 wv = wr[i];
            acc[4*i+0] += xv * wv.x;
            acc[4*i+1] += xv * wv.y;
            acc[4*i+2] += xv * wv.z;
            acc[4*i+3] += xv * wv.w;
        }
    }
}

__global__ void __launch_bounds__(256, 1)
gnn_kernel(const float* __restrict__ W2,  // [128,64]
           const float* __restrict__ b2,  // [64]
           float* __restrict__ out)       // [T][N][64]
{
    extern __shared__ float sm[];
    float* Wb  = sm;            // 4096
    float* Xs  = sm + 4096;     // 256*65
    float* Vs  = Xs + 256 * 65; // 256*65
    float* Acc = Vs + 256 * 65; // 256*65

    int tid = threadIdx.x;
    int t   = blockIdx.x;
    const float* Xg = g_Hout + (size_t)t * NN * 64;

    // Phase A: load X tile (padded), M1 weights, Acc := Cp
    for (int idx = tid; idx < NN * 64; idx += 256) {
        int n = idx >> 6, c = idx & 63;
        Xs[n * 65 + c]  = Xg[idx];
        Acc[n * 65 + c] = g_Cp[idx];
    }
    for (int idx = tid; idx < 4096; idx += 256) Wb[idx] = g_M1[idx];
    __syncthreads();

    // Phase B1: V = X @ M1  (thread-per-node)
    {
        float acc[64];
        gemv64(Xs + tid * 65, Wb, acc);
#pragma unroll
        for (int c = 0; c < 64; c++) Vs[tid * 65 + c] = acc[c];
    }
    __syncthreads();
    for (int idx = tid; idx < 4096; idx += 256) Wb[idx] = g_M2[idx];
    __syncthreads();

    // Phase B2: Acc = (deg * (X@M2) + Cp)/d + b2
    {
        float acc[64];
        gemv64(Xs + tid * 65, Wb, acc);
        float dg = (float)g_deg[tid];
        float dinv = 1.f / fmaxf(dg, 1.f);
#pragma unroll
        for (int c = 0; c < 64; c++)
            Acc[tid * 65 + c] = (acc[c] * dg + Acc[tid * 65 + c]) * dinv + b2[c];
    }
    __syncthreads();
    for (int idx = tid; idx < 4096; idx += 256) Wb[idx] = W2[idx]; // W2a rows 0..63
    __syncthreads();

    // Phase B3: Acc += X @ W2a
    {
        float acc[64];
        gemv64(Xs + tid * 65, Wb, acc);
#pragma unroll
        for (int c = 0; c < 64; c++) Acc[tid * 65 + c] += acc[c];
    }
    __syncthreads();

    // Phase C: warp-per-node gather of V over incoming edges; coalesced store
    int warp = tid >> 5, lane = tid & 31;
    for (int n = warp; n < NN; n += 8) {
        int lo = g_off[n], hi = g_off[n + 1];
        float s0 = 0.f, s1 = 0.f;
        int e = lo;
        for (; e + 4 <= hi; e += 4) {
            int i0 = g_src[e], i1 = g_src[e + 1], i2 = g_src[e + 2], i3 = g_src[e + 3];
            s0 += Vs[i0 * 65 + lane]      + Vs[i1 * 65 + lane]
                + Vs[i2 * 65 + lane]      + Vs[i3 * 65 + lane];
            s1 += Vs[i0 * 65 + 32 + lane] + Vs[i1 * 65 + 32 + lane]
                + Vs[i2 * 65 + 32 + lane] + Vs[i3 * 65 + 32 + lane];
        }
        for (; e < hi; e++) {
            int i0 = g_src[e];
            s0 += Vs[i0 * 65 + lane];
            s1 += Vs[i0 * 65 + 32 + lane];
        }
        float dinv = 1.f / fmaxf((float)g_deg[n], 1.f);
        float* op = out + ((size_t)t * NN + n) * 64;
        op[lane]      = Acc[n * 65 + lane]      + s0 * dinv;
        op[32 + lane] = Acc[n * 65 + 32 + lane] + s1 * dinv;
    }
}

// ---------------- launch ----------------
extern "C" void kernel_launch(void* const* d_in, const int* in_sizes, int n_in,
                              void* d_out, int out_size)
{
    const float* aqi  = (const float*)d_in[0];
    const int*   conn = (const int*)  d_in[1];
    const float* cw   = (const float*)d_in[2];
    const float* embW = (const float*)d_in[3];
    const float* embB = (const float*)d_in[4];
    const float* Wih  = (const float*)d_in[5];
    const float* Whh  = (const float*)d_in[6];
    const float* bih  = (const float*)d_in[7];
    const float* bhh  = (const float*)d_in[8];
    const float* W1   = (const float*)d_in[9];
    const float* b1   = (const float*)d_in[10];
    const float* W2   = (const float*)d_in[11];
    const float* b2   = (const float*)d_in[12];
    float* out = (float*)d_out;

    setup_kernel<<<1, 256>>>(conn, cw, W1, b1, W2);
    lstm_kernel<<<BN / S_LSTM, 256>>>(aqi, embW, embB, Wih, Whh, bih, bhh);
    cudaFuncSetAttribute(gnn_kernel, cudaFuncAttributeMaxDynamicSharedMemorySize,
                         GNN_SMEM_BYTES);
    gnn_kernel<<<TT, 256, GNN_SMEM_BYTES>>>(W2, b2, out);
}

// round 2
// speedup vs baseline: 1.0255x; 1.0255x over previous
#include <cuda_runtime.h>

#define BB 16
#define LL 24
#define NN 256
#define EE 4096
#define HH 64
#define TT (BB*LL)      // 384 graphs
#define BN (BB*NN)      // 4096 LSTM samples
#define S_LSTM 16       // samples per LSTM block

// ---------------- packed f32x2 helpers ----------------
__device__ __forceinline__ unsigned long long packf2(float lo, float hi) {
    unsigned long long r;
    asm("mov.b64 %0,{%1,%2};" : "=l"(r) : "f"(lo), "f"(hi));
    return r;
}
__device__ __forceinline__ void unpackf2(unsigned long long v, float& lo, float& hi) {
    asm("mov.b64 {%0,%1},%2;" : "=f"(lo), "=f"(hi) : "l"(v));
}
__device__ __forceinline__ void ffma2(unsigned long long& d, unsigned long long a,
                                      unsigned long long b) {
    asm("fma.rn.f32x2 %0,%1,%2,%0;" : "+l"(d) : "l"(a), "l"(b));
}

// ---------------- device scratch ----------------
__device__ float g_Hout[TT * NN * HH];     // [t][n][64]
__device__ float g_M1[64 * 64];            // W1a @ W2b
__device__ float g_M2[64 * 64];            // W1b @ W2b
__device__ float g_Wc[64 * 64];            // W2a + M2
__device__ float g_Cp[NN * 64];            // per-node constant (through W2b)
__device__ int   g_deg[NN];
__device__ int   g_off[NN + 1];
__device__ int   g_src[EE];

// ---------------- setup ----------------
__global__ void setup_kernel(const int* __restrict__ conn,
                             const float* __restrict__ city_w,
                             const float* __restrict__ W1,   // [130,64]
                             const float* __restrict__ b1,   // [64]
                             const float* __restrict__ W2)   // [128,64]
{
    __shared__ float s0[NN], s1[NN];
    __shared__ int degs[NN], cur[NN], scan[NN];
    __shared__ float W2s[64 * 64];   // W2b (rows 64..127), 16 KB
    __shared__ float G0[64], G1[64], Gb[64];
    int t = threadIdx.x;

    s0[t] = 0.f; s1[t] = 0.f; degs[t] = 0;
    for (int idx = t; idx < 4096; idx += 256) W2s[idx] = W2[4096 + idx];
    __syncthreads();

    const int* row = conn;
    const int* col = conn + EE;
    for (int e = t; e < EE; e += 256) {
        int c = col[e];
        atomicAdd(&degs[c], 1);
        atomicAdd(&s0[c], city_w[2 * e + 0]);
        atomicAdd(&s1[c], city_w[2 * e + 1]);
    }
    __syncthreads();

    // inclusive scan of degs (Hillis-Steele)
    scan[t] = degs[t];
    __syncthreads();
    for (int d = 1; d < 256; d <<= 1) {
        int v = (t >= d) ? scan[t - d] : 0;
        __syncthreads();
        scan[t] += v;
        __syncthreads();
    }
    int excl = scan[t] - degs[t];
    g_off[t] = excl;
    if (t == 255) g_off[256] = scan[255];
    cur[t] = excl;
    g_deg[t] = degs[t];
    __syncthreads();

    for (int e = t; e < EE; e += 256) {
        int c = col[e];
        int p = atomicAdd(&cur[c], 1);
        g_src[p] = row[e];
    }

    // M1/M2/Wc with W2b staged in smem
    for (int idx = t; idx < 4096; idx += 256) {
        int k = idx >> 6, c = idx & 63;
        float a1 = 0.f, a2 = 0.f;
        const float* w1a = W1 + k * 64;
        const float* w1b = W1 + 4096 + k * 64;
#pragma unroll 4
        for (int j = 0; j < 64; j++) {
            float w2 = W2s[j * 64 + c];
            a1 += w1a[j] * w2;
            a2 += w1b[j] * w2;
        }
        g_M1[idx] = a1;
        g_M2[idx] = a2;
        g_Wc[idx] = W2[idx] + a2;   // W2a + M2
    }
    if (t < 64) {
        float a0 = 0.f, a1 = 0.f, ab = 0.f;
#pragma unroll 4
        for (int k = 0; k < 64; k++) {
            float w2 = W2s[k * 64 + t];
            a0 += W1[128 * 64 + k] * w2;
            a1 += W1[129 * 64 + k] * w2;
            ab += b1[k] * w2;
        }
        G0[t] = a0; G1[t] = a1; Gb[t] = ab;
    }
    __syncthreads();
    for (int idx = t; idx < NN * 64; idx += 256) {
        int n = idx >> 6, c = idx & 63;
        g_Cp[idx] = s0[n] * G0[c] + s1[n] * G1[c] + (float)degs[n] * Gb[c];
    }
}

// ---------------- LSTM ----------------
__device__ __forceinline__ float fsig(float x) { return 1.f / (1.f + __expf(-x)); }
__device__ __forceinline__ float ftanh(float x) {
    float e = __expf(2.f * fabsf(x));
    float t = 1.f - 2.f / (e + 1.f);
    return copysignf(t, x);
}

__global__ void __launch_bounds__(256, 2)
lstm_kernel(const float* __restrict__ aqi,   // [B,24,N,1]
            const float* __restrict__ embW,  // [1,16]
            const float* __restrict__ embB,  // [16]
            const float* __restrict__ Wih,   // [256,16]
            const float* __restrict__ Whh,   // [256,64]
            const float* __restrict__ bih,   // [256]
            const float* __restrict__ bhh)   // [256]
{
    __shared__ __align__(16) float hS[S_LSTM][64];
    __shared__ __align__(16) float cS[S_LSTM][64];
    __shared__ float gS[S_LSTM][256];
    __shared__ float aS[S_LSTM][LL];

    int tid = threadIdx.x;         // gate row r
    int m0  = blockIdx.x * S_LSTM;

    // W_hh row r, packed into 32 f32x2 registers
    unsigned long long w2[32];
    {
        const ulonglong2* wr = (const ulonglong2*)(Whh + tid * 64);
#pragma unroll
        for (int i = 0; i < 16; i++) {
            ulonglong2 v = wr[i];
            w2[2 * i] = v.x; w2[2 * i + 1] = v.y;
        }
    }
    float A = 0.f, Bc = 0.f;
#pragma unroll
    for (int j = 0; j < 16; j++) {
        float wi = Wih[tid * 16 + j];
        A  += wi * embW[j];
        Bc += wi * embB[j];
    }
    Bc += bih[tid] + bhh[tid];

    for (int idx = tid; idx < S_LSTM * LL; idx += 256) {
        int s = idx / LL, l = idx % LL;
        int m = m0 + s; int b = m >> 8; int n = m & 255;
        aS[s][l] = aqi[(b * LL + l) * NN + n];
    }
    for (int idx = tid; idx < S_LSTM * 64; idx += 256) {
        ((float*)hS)[idx] = 0.f; ((float*)cS)[idx] = 0.f;
    }
    __syncthreads();

    for (int l = 0; l < LL; l++) {
#pragma unroll 2
        for (int s = 0; s < S_LSTM; s++) {
            unsigned long long a0 = 0ull, a1 = 0ull, a2 = 0ull, a3 = 0ull;
            const ulonglong2* hp = (const ulonglong2*)hS[s];
#pragma unroll
            for (int i = 0; i < 8; i++) {
                ulonglong2 h0 = hp[2 * i];
                ulonglong2 h1 = hp[2 * i + 1];
                ffma2(a0, h0.x, w2[4 * i + 0]);
                ffma2(a1, h0.y, w2[4 * i + 1]);
                ffma2(a2, h1.x, w2[4 * i + 2]);
                ffma2(a3, h1.y, w2[4 * i + 3]);
            }
            float l0, h0f, l1, h1f, l2, h2f, l3, h3f;
            unpackf2(a0, l0, h0f); unpackf2(a1, l1, h1f);
            unpackf2(a2, l2, h2f); unpackf2(a3, l3, h3f);
            gS[s][tid] = aS[s][l] * A + Bc +
                         (((l0 + h0f) + (l1 + h1f)) + ((l2 + h2f) + (l3 + h3f)));
        }
        __syncthreads();
#pragma unroll
        for (int u = 0; u < (S_LSTM * 64) / 256; u++) {
            int idx = u * 256 + tid;
            int s = idx >> 6, j = idx & 63;
            float gi = gS[s][j];
            float gf = gS[s][64 + j];
            float gg = gS[s][128 + j];
            float go = gS[s][192 + j];
            float cn = fsig(gf) * cS[s][j] + fsig(gi) * ftanh(gg);
            float hn = fsig(go) * ftanh(cn);
            cS[s][j] = cn; hS[s][j] = hn;
            int m = m0 + s; int b = m >> 8; int n = m & 255;
            g_Hout[(((b * LL + l) * NN) + n) * 64 + j] = hn;
        }
        __syncthreads();
    }
}

// ---------------- GNN: one block per graph ----------------
#define GNN_SMEM_FLOATS (4096 + 64 + 3 * 256 * 65)
#define GNN_SMEM_BYTES  (GNN_SMEM_FLOATS * 4)

// packed gemv: out[0..63] for one node row (xrow in smem, Wb broadcast in smem)
__device__ __forceinline__ void gemv64p(const float* __restrict__ xrow,
                                        const float* __restrict__ Wb,
                                        unsigned long long* acc)
{
#pragma unroll
    for (int i = 0; i < 32; i++) acc[i] = 0ull;
#pragma unroll 4
    for (int k = 0; k < 64; k++) {
        float xk = xrow[k];
        unsigned long long xx = packf2(xk, xk);
        const ulonglong2* wr = (const ulonglong2*)(Wb + (k << 6));
#pragma unroll
        for (int i = 0; i < 16; i++) {
            ulonglong2 wv = wr[i];
            ffma2(acc[2 * i + 0], xx, wv.x);
            ffma2(acc[2 * i + 1], xx, wv.y);
        }
    }
}

__global__ void __launch_bounds__(256, 1)
gnn_kernel(const float* __restrict__ b2,  // [64]
           float* __restrict__ out)       // [T][N][64]
{
    extern __shared__ __align__(16) float sm[];
    float* Wb  = sm;                 // 4096
    float* b2s = sm + 4096;          // 64
    float* Xs  = b2s + 64;           // 256*65
    float* Vs  = Xs + 256 * 65;
    float* Acc = Vs + 256 * 65;

    int tid = threadIdx.x;
    int t   = blockIdx.x;
    const float* Xg = g_Hout + (size_t)t * NN * 64;

    // Phase A: load X (padded 65), M1 weights, b2
    for (int idx = tid; idx < NN * 64; idx += 256) {
        Xs[(idx >> 6) * 65 + (idx & 63)] = Xg[idx];
    }
    for (int idx = tid; idx < 4096; idx += 256) Wb[idx] = g_M1[idx];
    if (tid < 64) b2s[tid] = b2[tid];
    __syncthreads();

    // Phase B1: V = X @ M1
    {
        unsigned long long acc[32];
        gemv64p(Xs + tid * 65, Wb, acc);
        float* vp = Vs + tid * 65;
#pragma unroll
        for (int i = 0; i < 32; i++) {
            float lo, hi; unpackf2(acc[i], lo, hi);
            vp[2 * i] = lo; vp[2 * i + 1] = hi;
        }
    }
    __syncthreads();
    for (int idx = tid; idx < 4096; idx += 256) Wb[idx] = g_Wc[idx];
    __syncthreads();

    // Phase B2: Z = X @ (W2a + M2)  (+ rare deg==0 correction -> X @ W2a)
    {
        unsigned long long acc[32];
        gemv64p(Xs + tid * 65, Wb, acc);
        float* ap = Acc + tid * 65;
#pragma unroll
        for (int i = 0; i < 32; i++) {
            float lo, hi; unpackf2(acc[i], lo, hi);
            ap[2 * i] = lo + b2s[2 * i]; ap[2 * i + 1] = hi + b2s[2 * i + 1];
        }
        if (g_deg[tid] == 0) {   // exact rare path: subtract X@M2
            const float* xr = Xs + tid * 65;
            for (int c = 0; c < 64; c++) {
                float s = 0.f;
                for (int k = 0; k < 64; k++) s += xr[k] * g_M2[k * 64 + c];
                ap[c] -= s;
            }
        }
    }
    __syncthreads();

    // Phase C: warp-per-node gather of V over incoming edges
    int warp = tid >> 5, lane = tid & 31;
    for (int n = warp; n < NN; n += 8) {
        int lo = g_off[n], hi = g_off[n + 1];
        float s0 = 0.f, s1 = 0.f;
        int e = lo;
        for (; e + 4 <= hi; e += 4) {
            int i0 = g_src[e], i1 = g_src[e + 1], i2 = g_src[e + 2], i3 = g_src[e + 3];
            s0 += Vs[i0 * 65 + lane]      + Vs[i1 * 65 + lane]
                + Vs[i2 * 65 + lane]      + Vs[i3 * 65 + lane];
            s1 += Vs[i0 * 65 + 32 + lane] + Vs[i1 * 65 + 32 + lane]
                + Vs[i2 * 65 + 32 + lane] + Vs[i3 * 65 + 32 + lane];
        }
        for (; e < hi; e++) {
            int i0 = g_src[e];
            s0 += Vs[i0 * 65 + lane];
            s1 += Vs[i0 * 65 + 32 + lane];
        }
        float dinv = 1.f / fmaxf((float)g_deg[n], 1.f);
        float* op = out + ((size_t)t * NN + n) * 64;
        op[lane]      = Acc[n * 65 + lane]      + (s0 + g_Cp[n * 64 + lane])      * dinv;
        op[32 + lane] = Acc[n * 65 + 32 + lane] + (s1 + g_Cp[n * 64 + 32 + lane]) * dinv;
    }
}

// ---------------- launch ----------------
extern "C" void kernel_launch(void* const* d_in, const int* in_sizes, int n_in,
                              void* d_out, int out_size)
{
    const float* aqi  = (const float*)d_in[0];
    const int*   conn = (const int*)  d_in[1];
    const float* cw   = (const float*)d_in[2];
    const float* embW = (const float*)d_in[3];
    const float* embB = (const float*)d_in[4];
    const float* Wih  = (const float*)d_in[5];
    const float* Whh  = (const float*)d_in[6];
    const float* bih  = (const float*)d_in[7];
    const float* bhh  = (const float*)d_in[8];
    const float* W1   = (const float*)d_in[9];
    const float* b1   = (const float*)d_in[10];
    const float* W2   = (const float*)d_in[11];
    const float* b2   = (const float*)d_in[12];
    float* out = (float*)d_out;

    setup_kernel<<<1, 256>>>(conn, cw, W1, b1, W2);
    lstm_kernel<<<BN / S_LSTM, 256>>>(aqi, embW, embB, Wih, Whh, bih, bhh);
    cudaFuncSetAttribute(gnn_kernel, cudaFuncAttributeMaxDynamicSharedMemorySize,
                         GNN_SMEM_BYTES);
    gnn_kernel<<<TT, 256, GNN_SMEM_BYTES>>>(b2, out);
}

// round 3
// speedup vs baseline: 1.1809x; 1.1515x over previous
#include <cuda_runtime.h>

#define BB 16
#define LL 24
#define NN 256
#define EE 4096
#define HH 64
#define TT (BB*LL)      // 384 graphs
#define BN (BB*NN)      // 4096 LSTM samples
#define S_LSTM 16

// ---------------- packed f32x2 helpers ----------------
__device__ __forceinline__ unsigned long long packf2(float lo, float hi) {
    unsigned long long r;
    asm("mov.b64 %0,{%1,%2};" : "=l"(r) : "f"(lo), "f"(hi));
    return r;
}
__device__ __forceinline__ void unpackf2(unsigned long long v, float& lo, float& hi) {
    asm("mov.b64 {%0,%1},%2;" : "=f"(lo), "=f"(hi) : "l"(v));
}
__device__ __forceinline__ void ffma2(unsigned long long& d, unsigned long long a,
                                      unsigned long long b) {
    asm("fma.rn.f32x2 %0,%1,%2,%0;" : "+l"(d) : "l"(a), "l"(b));
}
__device__ __forceinline__ float tanha(float x) {
    float r; asm("tanh.approx.f32 %0,%1;" : "=f"(r) : "f"(x)); return r;
}
__device__ __forceinline__ float fsig(float x) { return 0.5f * tanha(0.5f * x) + 0.5f; }

// ---------------- device scratch ----------------
__device__ float g_Hout[TT * NN * HH];
__device__ float g_M1[64 * 64];
__device__ float g_M2[64 * 64];
__device__ float g_Wc[64 * 64];
__device__ float g_Cp[NN * 64];
__device__ float g_G0[64], g_G1[64], g_Gb[64];
__device__ float g_s0[NN], g_s1[NN];
__device__ int   g_deg[NN];
__device__ int   g_off[NN + 1];
__device__ int   g_src[EE];

// ---------------- setup part 1: graph/CSR (1 block, 1024 threads) ----------------
__global__ void setup_graph(const int* __restrict__ conn,
                            const float* __restrict__ city_w)
{
    __shared__ float s0[NN], s1[NN];
    __shared__ int degs[NN], cur[NN], scan[NN];
    int t = threadIdx.x;

    if (t < NN) { s0[t] = 0.f; s1[t] = 0.f; degs[t] = 0; }
    __syncthreads();

    const int* row = conn;
    const int* col = conn + EE;
#pragma unroll
    for (int u = 0; u < EE / 1024; u++) {
        int e = u * 1024 + t;
        int c = col[e];
        atomicAdd(&degs[c], 1);
        atomicAdd(&s0[c], city_w[2 * e + 0]);
        atomicAdd(&s1[c], city_w[2 * e + 1]);
    }
    __syncthreads();

    if (t < NN) scan[t] = degs[t];
    __syncthreads();
    for (int d = 1; d < NN; d <<= 1) {
        int v = (t < NN && t >= d) ? scan[t - d] : 0;
        __syncthreads();
        if (t < NN) scan[t] += v;
        __syncthreads();
    }
    if (t < NN) {
        int excl = scan[t] - degs[t];
        g_off[t] = excl;
        cur[t] = excl;
        g_deg[t] = degs[t];
        g_s0[t] = s0[t];
        g_s1[t] = s1[t];
        if (t == NN - 1) g_off[NN] = scan[NN - 1];
    }
    __syncthreads();
#pragma unroll
    for (int u = 0; u < EE / 1024; u++) {
        int e = u * 1024 + t;
        int c = col[e];
        int p = atomicAdd(&cur[c], 1);
        g_src[p] = row[e];
    }
}

// ---------------- setup part 2: weight folds (65 blocks x 64 threads) ----------------
__global__ void setup_mm(const float* __restrict__ W1,   // [130,64]
                         const float* __restrict__ b1,   // [64]
                         const float* __restrict__ W2)   // [128,64]
{
    int c = threadIdx.x;
    int k = blockIdx.x;
    const float* W2b = W2 + 4096;
    if (k < 64) {
        __shared__ float w1a[64], w1b[64];
        if (c < 64) { w1a[c] = W1[k * 64 + c]; w1b[c] = W1[4096 + k * 64 + c]; }
        __syncthreads();
        float p0 = 0.f, p1 = 0.f, p2 = 0.f, p3 = 0.f;
        float q0 = 0.f, q1 = 0.f, q2 = 0.f, q3 = 0.f;
#pragma unroll
        for (int j = 0; j < 64; j += 4) {
            float v0 = W2b[(j + 0) * 64 + c];
            float v1 = W2b[(j + 1) * 64 + c];
            float v2 = W2b[(j + 2) * 64 + c];
            float v3 = W2b[(j + 3) * 64 + c];
            p0 += w1a[j + 0] * v0; q0 += w1b[j + 0] * v0;
            p1 += w1a[j + 1] * v1; q1 += w1b[j + 1] * v1;
            p2 += w1a[j + 2] * v2; q2 += w1b[j + 2] * v2;
            p3 += w1a[j + 3] * v3; q3 += w1b[j + 3] * v3;
        }
        float a1 = (p0 + p1) + (p2 + p3);
        float a2 = (q0 + q1) + (q2 + q3);
        g_M1[k * 64 + c] = a1;
        g_M2[k * 64 + c] = a2;
        g_Wc[k * 64 + c] = W2[k * 64 + c] + a2;
    } else {
        float a0 = 0.f, a1 = 0.f, ab = 0.f;
#pragma unroll 8
        for (int j = 0; j < 64; j++) {
            float w2 = W2b[j * 64 + c];
            a0 += W1[128 * 64 + j] * w2;
            a1 += W1[129 * 64 + j] * w2;
            ab += b1[j] * w2;
        }
        g_G0[c] = a0; g_G1[c] = a1; g_Gb[c] = ab;
    }
}

// ---------------- setup part 3: per-node constant ----------------
__global__ void setup_cp()
{
    int idx = blockIdx.x * 256 + threadIdx.x;   // 64 blocks x 256 = 16384
    int n = idx >> 6, c = idx & 63;
    g_Cp[idx] = g_s0[n] * g_G0[c] + g_s1[n] * g_G1[c] + (float)g_deg[n] * g_Gb[c];
}

// ---------------- LSTM ----------------
__global__ void __launch_bounds__(256)
lstm_kernel(const float* __restrict__ aqi,
            const float* __restrict__ embW,
            const float* __restrict__ embB,
            const float* __restrict__ Wih,
            const float* __restrict__ Whh,
            const float* __restrict__ bih,
            const float* __restrict__ bhh)
{
    __shared__ __align__(16) float hS[S_LSTM][64];
    __shared__ __align__(16) float cS[S_LSTM][64];
    __shared__ float gS[S_LSTM][256];
    __shared__ float aS[S_LSTM][LL];

    int tid = threadIdx.x;
    int m0  = blockIdx.x * S_LSTM;

    unsigned long long w2[32];
    {
        const ulonglong2* wr = (const ulonglong2*)(Whh + tid * 64);
#pragma unroll
        for (int i = 0; i < 16; i++) {
            ulonglong2 v = wr[i];
            w2[2 * i] = v.x; w2[2 * i + 1] = v.y;
        }
    }
    float A = 0.f, Bc = 0.f;
#pragma unroll
    for (int j = 0; j < 16; j++) {
        float wi = Wih[tid * 16 + j];
        A  += wi * embW[j];
        Bc += wi * embB[j];
    }
    Bc += bih[tid] + bhh[tid];

    for (int idx = tid; idx < S_LSTM * LL; idx += 256) {
        int s = idx / LL, l = idx % LL;
        int m = m0 + s; int b = m >> 8; int n = m & 255;
        aS[s][l] = aqi[(b * LL + l) * NN + n];
    }
    for (int idx = tid; idx < S_LSTM * 64; idx += 256) {
        ((float*)hS)[idx] = 0.f; ((float*)cS)[idx] = 0.f;
    }
    __syncthreads();

    for (int l = 0; l < LL; l++) {
#pragma unroll 2
        for (int s = 0; s < S_LSTM; s++) {
            unsigned long long a0 = 0ull, a1 = 0ull, a2 = 0ull, a3 = 0ull;
            const ulonglong2* hp = (const ulonglong2*)hS[s];
#pragma unroll
            for (int i = 0; i < 8; i++) {
                ulonglong2 h0 = hp[2 * i];
                ulonglong2 h1 = hp[2 * i + 1];
                ffma2(a0, h0.x, w2[4 * i + 0]);
                ffma2(a1, h0.y, w2[4 * i + 1]);
                ffma2(a2, h1.x, w2[4 * i + 2]);
                ffma2(a3, h1.y, w2[4 * i + 3]);
            }
            float l0, h0f, l1, h1f, l2, h2f, l3, h3f;
            unpackf2(a0, l0, h0f); unpackf2(a1, l1, h1f);
            unpackf2(a2, l2, h2f); unpackf2(a3, l3, h3f);
            gS[s][tid] = aS[s][l] * A + Bc +
                         (((l0 + h0f) + (l1 + h1f)) + ((l2 + h2f) + (l3 + h3f)));
        }
        __syncthreads();
#pragma unroll
        for (int u = 0; u < (S_LSTM * 64) / 256; u++) {
            int idx = u * 256 + tid;
            int s = idx >> 6, j = idx & 63;
            float gi = gS[s][j];
            float gf = gS[s][64 + j];
            float gg = gS[s][128 + j];
            float go = gS[s][192 + j];
            float cn = fsig(gf) * cS[s][j] + fsig(gi) * tanha(gg);
            float hn = fsig(go) * tanha(cn);
            cS[s][j] = cn; hS[s][j] = hn;
            int m = m0 + s; int b = m >> 8; int n = m & 255;
            g_Hout[(((b * LL + l) * NN) + n) * 64 + j] = hn;
        }
        __syncthreads();
    }
}

// ---------------- GNN ----------------
#define GNN_SMEM_FLOATS (4096 + 64 + 3 * 256 * 65)
#define GNN_SMEM_BYTES  (GNN_SMEM_FLOATS * 4)

__device__ __forceinline__ void gemv64p(const float* __restrict__ xrow,
                                        const float* __restrict__ Wb,
                                        unsigned long long* acc)
{
#pragma unroll
    for (int i = 0; i < 32; i++) acc[i] = 0ull;
#pragma unroll 4
    for (int k = 0; k < 64; k++) {
        float xk = xrow[k];
        unsigned long long xx = packf2(xk, xk);
        const ulonglong2* wr = (const ulonglong2*)(Wb + (k << 6));
#pragma unroll
        for (int i = 0; i < 16; i++) {
            ulonglong2 wv = wr[i];
            ffma2(acc[2 * i + 0], xx, wv.x);
            ffma2(acc[2 * i + 1], xx, wv.y);
        }
    }
}

__global__ void __launch_bounds__(256, 1)
gnn_kernel(const float* __restrict__ b2,
           float* __restrict__ out)
{
    extern __shared__ __align__(16) float sm[];
    float* Wb  = sm;
    float* b2s = sm + 4096;
    float* Xs  = b2s + 64;
    float* Vs  = Xs + 256 * 65;
    float* Acc = Vs + 256 * 65;

    int tid = threadIdx.x;
    int t   = blockIdx.x;
    const float* Xg = g_Hout + (size_t)t * NN * 64;

    for (int idx = tid; idx < NN * 64; idx += 256) {
        Xs[(idx >> 6) * 65 + (idx & 63)] = Xg[idx];
    }
    for (int idx = tid; idx < 4096; idx += 256) Wb[idx] = g_M1[idx];
    if (tid < 64) b2s[tid] = b2[tid];
    __syncthreads();

    {
        unsigned long long acc[32];
        gemv64p(Xs + tid * 65, Wb, acc);
        float* vp = Vs + tid * 65;
#pragma unroll
        for (int i = 0; i < 32; i++) {
            float lo, hi; unpackf2(acc[i], lo, hi);
            vp[2 * i] = lo; vp[2 * i + 1] = hi;
        }
    }
    __syncthreads();
    for (int idx = tid; idx < 4096; idx += 256) Wb[idx] = g_Wc[idx];
    __syncthreads();

    {
        unsigned long long acc[32];
        gemv64p(Xs + tid * 65, Wb, acc);
        float* ap = Acc + tid * 65;
#pragma unroll
        for (int i = 0; i < 32; i++) {
            float lo, hi; unpackf2(acc[i], lo, hi);
            ap[2 * i] = lo + b2s[2 * i]; ap[2 * i + 1] = hi + b2s[2 * i + 1];
        }
        if (g_deg[tid] == 0) {
            const float* xr = Xs + tid * 65;
            for (int c = 0; c < 64; c++) {
                float s = 0.f;
                for (int k = 0; k < 64; k++) s += xr[k] * g_M2[k * 64 + c];
                ap[c] -= s;
            }
        }
    }
    __syncthreads();

    int warp = tid >> 5, lane = tid & 31;
    for (int n = warp; n < NN; n += 8) {
        int lo = g_off[n], hi = g_off[n + 1];
        float s0 = 0.f, s1 = 0.f;
        int e = lo;
        for (; e + 4 <= hi; e += 4) {
            int i0 = g_src[e], i1 = g_src[e + 1], i2 = g_src[e + 2], i3 = g_src[e + 3];
            s0 += Vs[i0 * 65 + lane]      + Vs[i1 * 65 + lane]
                + Vs[i2 * 65 + lane]      + Vs[i3 * 65 + lane];
            s1 += Vs[i0 * 65 + 32 + lane] + Vs[i1 * 65 + 32 + lane]
                + Vs[i2 * 65 + 32 + lane] + Vs[i3 * 65 + 32 + lane];
        }
        for (; e < hi; e++) {
            int i0 = g_src[e];
            s0 += Vs[i0 * 65 + lane];
            s1 += Vs[i0 * 65 + 32 + lane];
        }
        float dinv = 1.f / fmaxf((float)g_deg[n], 1.f);
        float* op = out + ((size_t)t * NN + n) * 64;
        op[lane]      = Acc[n * 65 + lane]      + (s0 + g_Cp[n * 64 + lane])      * dinv;
        op[32 + lane] = Acc[n * 65 + 32 + lane] + (s1 + g_Cp[n * 64 + 32 + lane]) * dinv;
    }
}

// ---------------- launch ----------------
extern "C" void kernel_launch(void* const* d_in, const int* in_sizes, int n_in,
                              void* d_out, int out_size)
{
    const float* aqi  = (const float*)d_in[0];
    const int*   conn = (const int*)  d_in[1];
    const float* cw   = (const float*)d_in[2];
    const float* embW = (const float*)d_in[3];
    const float* embB = (const float*)d_in[4];
    const float* Wih  = (const float*)d_in[5];
    const float* Whh  = (const float*)d_in[6];
    const float* bih  = (const float*)d_in[7];
    const float* bhh  = (const float*)d_in[8];
    const float* W1   = (const float*)d_in[9];
    const float* b1   = (const float*)d_in[10];
    const float* W2   = (const float*)d_in[11];
    const float* b2   = (const float*)d_in[12];
    float* out = (float*)d_out;

    lstm_kernel<<<BN / S_LSTM, 256>>>(aqi, embW, embB, Wih, Whh, bih, bhh);
    setup_graph<<<1, 1024>>>(conn, cw);
    setup_mm<<<65, 64>>>(W1, b1, W2);
    setup_cp<<<64, 256>>>();
    cudaFuncSetAttribute(gnn_kernel, cudaFuncAttributeMaxDynamicSharedMemorySize,
                         GNN_SMEM_BYTES);
    gnn_kernel<<<TT, 256, GNN_SMEM_BYTES>>>(b2, out);
}

// round 4
// speedup vs baseline: 1.4101x; 1.1941x over previous
#include <cuda_runtime.h>

#define BB 16
#define LL 24
#define NN 256
#define EE 4096
#define HH 64
#define TT (BB*LL)      // 384 graphs
#define BN (BB*NN)      // 4096 LSTM samples
#define S_LSTM 16

// ---------------- packed f32x2 helpers ----------------
__device__ __forceinline__ unsigned long long packf2(float lo, float hi) {
    unsigned long long r;
    asm("mov.b64 %0,{%1,%2};" : "=l"(r) : "f"(lo), "f"(hi));
    return r;
}
__device__ __forceinline__ void unpackf2(unsigned long long v, float& lo, float& hi) {
    asm("mov.b64 {%0,%1},%2;" : "=f"(lo), "=f"(hi) : "l"(v));
}
__device__ __forceinline__ void ffma2(unsigned long long& d, unsigned long long a,
                                      unsigned long long b) {
    asm("fma.rn.f32x2 %0,%1,%2,%0;" : "+l"(d) : "l"(a), "l"(b));
}
__device__ __forceinline__ float tanha(float x) {
    float r; asm("tanh.approx.f32 %0,%1;" : "=f"(r) : "f"(x)); return r;
}
__device__ __forceinline__ float fsig(float x) { return 0.5f * tanha(0.5f * x) + 0.5f; }

// ---------------- device scratch ----------------
__device__ float g_Hout[TT * NN * HH];     // 25 MB
__device__ float g_V[TT * NN * HH];        // 25 MB
__device__ float g_M1[64 * 64];
__device__ float g_M2[64 * 64];
__device__ float g_Wc[64 * 64];
__device__ float g_G0[64], g_G1[64], g_Gb[64];
__device__ float g_s0v[NN], g_s1v[NN];
__device__ int   g_deg[NN];
__device__ int   g_off[NN + 1];
__device__ int   g_src[EE];

// ---------------- setup part 1: graph/CSR ----------------
__global__ void setup_graph(const int* __restrict__ conn,
                            const float* __restrict__ city_w)
{
    __shared__ float s0[NN], s1[NN];
    __shared__ int degs[NN], cur[NN], scan[NN];
    int t = threadIdx.x;

    if (t < NN) { s0[t] = 0.f; s1[t] = 0.f; degs[t] = 0; }
    __syncthreads();

    const int* row = conn;
    const int* col = conn + EE;
#pragma unroll
    for (int u = 0; u < EE / 1024; u++) {
        int e = u * 1024 + t;
        int c = col[e];
        atomicAdd(&degs[c], 1);
        atomicAdd(&s0[c], city_w[2 * e + 0]);
        atomicAdd(&s1[c], city_w[2 * e + 1]);
    }
    __syncthreads();

    if (t < NN) scan[t] = degs[t];
    __syncthreads();
    for (int d = 1; d < NN; d <<= 1) {
        int v = (t < NN && t >= d) ? scan[t - d] : 0;
        __syncthreads();
        if (t < NN) scan[t] += v;
        __syncthreads();
    }
    if (t < NN) {
        int excl = scan[t] - degs[t];
        g_off[t] = excl;
        cur[t] = excl;
        g_deg[t] = degs[t];
        g_s0v[t] = s0[t];
        g_s1v[t] = s1[t];
        if (t == NN - 1) g_off[NN] = scan[NN - 1];
    }
    __syncthreads();
#pragma unroll
    for (int u = 0; u < EE / 1024; u++) {
        int e = u * 1024 + t;
        int c = col[e];
        int p = atomicAdd(&cur[c], 1);
        g_src[p] = row[e];
    }
}

// ---------------- setup part 2: weight folds ----------------
__global__ void setup_mm(const float* __restrict__ W1,
                         const float* __restrict__ b1,
                         const float* __restrict__ W2)
{
    int c = threadIdx.x;
    int k = blockIdx.x;
    const float* W2b = W2 + 4096;
    if (k < 64) {
        __shared__ float w1a[64], w1b[64];
        if (c < 64) { w1a[c] = W1[k * 64 + c]; w1b[c] = W1[4096 + k * 64 + c]; }
        __syncthreads();
        float p0 = 0.f, p1 = 0.f, p2 = 0.f, p3 = 0.f;
        float q0 = 0.f, q1 = 0.f, q2 = 0.f, q3 = 0.f;
#pragma unroll
        for (int j = 0; j < 64; j += 4) {
            float v0 = W2b[(j + 0) * 64 + c];
            float v1 = W2b[(j + 1) * 64 + c];
            float v2 = W2b[(j + 2) * 64 + c];
            float v3 = W2b[(j + 3) * 64 + c];
            p0 += w1a[j + 0] * v0; q0 += w1b[j + 0] * v0;
            p1 += w1a[j + 1] * v1; q1 += w1b[j + 1] * v1;
            p2 += w1a[j + 2] * v2; q2 += w1b[j + 2] * v2;
            p3 += w1a[j + 3] * v3; q3 += w1b[j + 3] * v3;
        }
        float a1 = (p0 + p1) + (p2 + p3);
        float a2 = (q0 + q1) + (q2 + q3);
        g_M1[k * 64 + c] = a1;
        g_M2[k * 64 + c] = a2;
        g_Wc[k * 64 + c] = W2[k * 64 + c] + a2;
    } else {
        float a0 = 0.f, a1 = 0.f, ab = 0.f;
#pragma unroll 8
        for (int j = 0; j < 64; j++) {
            float w2 = W2b[j * 64 + c];
            a0 += W1[128 * 64 + j] * w2;
            a1 += W1[129 * 64 + j] * w2;
            ab += b1[j] * w2;
        }
        g_G0[c] = a0; g_G1[c] = a1; g_Gb[c] = ab;
    }
}

// ---------------- LSTM ----------------
__global__ void __launch_bounds__(256)
lstm_kernel(const float* __restrict__ aqi,
            const float* __restrict__ embW,
            const float* __restrict__ embB,
            const float* __restrict__ Wih,
            const float* __restrict__ Whh,
            const float* __restrict__ bih,
            const float* __restrict__ bhh)
{
    __shared__ __align__(16) float hS[S_LSTM][64];
    __shared__ __align__(16) float cS[S_LSTM][64];
    __shared__ __align__(16) float gS[S_LSTM][256];
    __shared__ float aS[S_LSTM][LL];

    int tid = threadIdx.x;
    int m0  = blockIdx.x * S_LSTM;

    unsigned long long w2[32];
    {
        const ulonglong2* wr = (const ulonglong2*)(Whh + tid * 64);
#pragma unroll
        for (int i = 0; i < 16; i++) {
            ulonglong2 v = wr[i];
            w2[2 * i] = v.x; w2[2 * i + 1] = v.y;
        }
    }
    float A = 0.f, Bc = 0.f;
#pragma unroll
    for (int j = 0; j < 16; j++) {
        float wi = Wih[tid * 16 + j];
        A  += wi * embW[j];
        Bc += wi * embB[j];
    }
    Bc += bih[tid] + bhh[tid];

    for (int idx = tid; idx < S_LSTM * LL; idx += 256) {
        int s = idx / LL, l = idx % LL;
        int m = m0 + s; int b = m >> 8; int n = m & 255;
        aS[s][l] = aqi[(b * LL + l) * NN + n];
    }
    for (int idx = tid; idx < S_LSTM * 64; idx += 256) {
        ((float*)hS)[idx] = 0.f; ((float*)cS)[idx] = 0.f;
    }
    __syncthreads();

    // epilogue mapping: thread -> (sample se, 4 gates j0..j0+3)
    int se = tid >> 4, j0 = (tid & 15) << 2;
    int me = m0 + se; int be = me >> 8; int ne = me & 255;
    float* hout_base = g_Hout + ((size_t)(be * LL) * NN + ne) * 64 + j0;

    for (int l = 0; l < LL; l++) {
#pragma unroll 2
        for (int s = 0; s < S_LSTM; s++) {
            unsigned long long a0 = 0ull, a1 = 0ull, a2 = 0ull, a3 = 0ull;
            const ulonglong2* hp = (const ulonglong2*)hS[s];
#pragma unroll
            for (int i = 0; i < 8; i++) {
                ulonglong2 h0 = hp[2 * i];
                ulonglong2 h1 = hp[2 * i + 1];
                ffma2(a0, h0.x, w2[4 * i + 0]);
                ffma2(a1, h0.y, w2[4 * i + 1]);
                ffma2(a2, h1.x, w2[4 * i + 2]);
                ffma2(a3, h1.y, w2[4 * i + 3]);
            }
            float l0, h0f, l1, h1f, l2, h2f, l3, h3f;
            unpackf2(a0, l0, h0f); unpackf2(a1, l1, h1f);
            unpackf2(a2, l2, h2f); unpackf2(a3, l3, h3f);
            gS[s][tid] = aS[s][l] * A + Bc +
                         (((l0 + h0f) + (l1 + h1f)) + ((l2 + h2f) + (l3 + h3f)));
        }
        __syncthreads();
        {
            float4 gi = *(const float4*)&gS[se][j0];
            float4 gf = *(const float4*)&gS[se][64 + j0];
            float4 gg = *(const float4*)&gS[se][128 + j0];
            float4 go = *(const float4*)&gS[se][192 + j0];
            float4 c4 = *(const float4*)&cS[se][j0];
            c4.x = fsig(gf.x) * c4.x + fsig(gi.x) * tanha(gg.x);
            c4.y = fsig(gf.y) * c4.y + fsig(gi.y) * tanha(gg.y);
            c4.z = fsig(gf.z) * c4.z + fsig(gi.z) * tanha(gg.z);
            c4.w = fsig(gf.w) * c4.w + fsig(gi.w) * tanha(gg.w);
            float4 h4;
            h4.x = fsig(go.x) * tanha(c4.x);
            h4.y = fsig(go.y) * tanha(c4.y);
            h4.z = fsig(go.z) * tanha(c4.z);
            h4.w = fsig(go.w) * tanha(c4.w);
            *(float4*)&cS[se][j0] = c4;
            *(float4*)&hS[se][j0] = h4;
            *(float4*)(hout_base + (size_t)l * NN * 64) = h4;
        }
        __syncthreads();
    }
}

// ---------------- GNN gemm: V = X@M1 -> g_V ; out = X@Wc + b2 ----------------
#define GEMM_SMEM_FLOATS (256 * 65 + 4096 + 64)
#define GEMM_SMEM_BYTES  (GEMM_SMEM_FLOATS * 4)

__device__ __forceinline__ void gemv64p(const float* __restrict__ xrow,
                                        const float* __restrict__ Wb,
                                        unsigned long long* acc)
{
#pragma unroll
    for (int i = 0; i < 32; i++) acc[i] = 0ull;
#pragma unroll 4
    for (int k = 0; k < 64; k++) {
        float xk = xrow[k];
        unsigned long long xx = packf2(xk, xk);
        const ulonglong2* wr = (const ulonglong2*)(Wb + (k << 6));
#pragma unroll
        for (int i = 0; i < 16; i++) {
            ulonglong2 wv = wr[i];
            ffma2(acc[2 * i + 0], xx, wv.x);
            ffma2(acc[2 * i + 1], xx, wv.y);
        }
    }
}

__global__ void __launch_bounds__(256)
gemm_kernel(const float* __restrict__ b2, float* __restrict__ out)
{
    extern __shared__ __align__(16) float sm[];
    float* Xs  = sm;                 // 256*65
    float* Wt  = sm + 256 * 65;      // 4096
    float* b2s = Wt + 4096;          // 64

    int tid = threadIdx.x;
    int t   = blockIdx.x;
    const float* Xg = g_Hout + (size_t)t * NN * 64;

    for (int idx = tid; idx < NN * 64; idx += 256)
        Xs[(idx >> 6) * 65 + (idx & 63)] = Xg[idx];
    for (int idx = tid; idx < 4096; idx += 256) Wt[idx] = g_M1[idx];
    if (tid < 64) b2s[tid] = b2[tid];
    __syncthreads();

    unsigned long long acc[32];
    // V = X @ M1
    gemv64p(Xs + tid * 65, Wt, acc);
    {
        float4* vp = (float4*)(g_V + (size_t)t * NN * 64 + tid * 64);
#pragma unroll
        for (int i = 0; i < 16; i++) {
            float4 v;
            unpackf2(acc[2 * i], v.x, v.y);
            unpackf2(acc[2 * i + 1], v.z, v.w);
            vp[i] = v;
        }
    }
    __syncthreads();
    for (int idx = tid; idx < 4096; idx += 256) Wt[idx] = g_Wc[idx];
    __syncthreads();

    // Z = X @ Wc + b2 -> out
    gemv64p(Xs + tid * 65, Wt, acc);
    {
        float* op = out + (size_t)t * NN * 64 + tid * 64;
        float4* op4 = (float4*)op;
#pragma unroll
        for (int i = 0; i < 16; i++) {
            float4 v;
            unpackf2(acc[2 * i], v.x, v.y);
            unpackf2(acc[2 * i + 1], v.z, v.w);
            v.x += b2s[4 * i];     v.y += b2s[4 * i + 1];
            v.z += b2s[4 * i + 2]; v.w += b2s[4 * i + 3];
            op4[i] = v;
        }
        if (g_deg[tid] == 0) {   // exact rare path: out = X@W2a + b2 = Z - X@M2
            const float* xr = Xs + tid * 65;
            for (int c = 0; c < 64; c++) {
                float s = 0.f;
                for (int k = 0; k < 64; k++) s += xr[k] * g_M2[k * 64 + c];
                op[c] -= s;
            }
        }
    }
}

// ---------------- GNN gather: out += (sum_in V + Cp)/deg ----------------
#define GATH_SMEM_FLOATS (256 * 65 + 192)
#define GATH_SMEM_BYTES  (GATH_SMEM_FLOATS * 4)

__global__ void __launch_bounds__(256)
gather_kernel(float* __restrict__ out)
{
    extern __shared__ __align__(16) float sm[];
    float* Vs  = sm;                  // 256*65
    float* G0s = sm + 256 * 65;       // 64
    float* G1s = G0s + 64;
    float* Gbs = G1s + 64;

    int tid = threadIdx.x;
    int t   = blockIdx.x;
    const float* Vg = g_V + (size_t)t * NN * 64;

    for (int idx = tid; idx < NN * 64; idx += 256)
        Vs[(idx >> 6) * 65 + (idx & 63)] = Vg[idx];
    if (tid < 64) { G0s[tid] = g_G0[tid]; G1s[tid] = g_G1[tid]; Gbs[tid] = g_Gb[tid]; }
    __syncthreads();

    int warp = tid >> 5, lane = tid & 31;
    for (int n = warp; n < NN; n += 8) {
        int lo = g_off[n], hi = g_off[n + 1];
        float a0 = 0.f, a1 = 0.f;
        int e = lo;
        for (; e + 4 <= hi; e += 4) {
            int i0 = g_src[e], i1 = g_src[e + 1], i2 = g_src[e + 2], i3 = g_src[e + 3];
            a0 += Vs[i0 * 65 + lane]      + Vs[i1 * 65 + lane]
                + Vs[i2 * 65 + lane]      + Vs[i3 * 65 + lane];
            a1 += Vs[i0 * 65 + 32 + lane] + Vs[i1 * 65 + 32 + lane]
                + Vs[i2 * 65 + 32 + lane] + Vs[i3 * 65 + 32 + lane];
        }
        for (; e < hi; e++) {
            int i0 = g_src[e];
            a0 += Vs[i0 * 65 + lane];
            a1 += Vs[i0 * 65 + 32 + lane];
        }
        float degf = (float)(hi - lo);
        float dinv = 1.f / fmaxf(degf, 1.f);
        float sn0 = g_s0v[n], sn1 = g_s1v[n];
        float cp0 = sn0 * G0s[lane]      + sn1 * G1s[lane]      + degf * Gbs[lane];
        float cp1 = sn0 * G0s[32 + lane] + sn1 * G1s[32 + lane] + degf * Gbs[32 + lane];
        float* op = out + ((size_t)t * NN + n) * 64;
        op[lane]      += (a0 + cp0) * dinv;
        op[32 + lane] += (a1 + cp1) * dinv;
    }
}

// ---------------- launch ----------------
extern "C" void kernel_launch(void* const* d_in, const int* in_sizes, int n_in,
                              void* d_out, int out_size)
{
    const float* aqi  = (const float*)d_in[0];
    const int*   conn = (const int*)  d_in[1];
    const float* cw   = (const float*)d_in[2];
    const float* embW = (const float*)d_in[3];
    const float* embB = (const float*)d_in[4];
    const float* Wih  = (const float*)d_in[5];
    const float* Whh  = (const float*)d_in[6];
    const float* bih  = (const float*)d_in[7];
    const float* bhh  = (const float*)d_in[8];
    const float* W1   = (const float*)d_in[9];
    const float* b1   = (const float*)d_in[10];
    const float* W2   = (const float*)d_in[11];
    const float* b2   = (const float*)d_in[12];
    float* out = (float*)d_out;

    lstm_kernel<<<BN / S_LSTM, 256>>>(aqi, embW, embB, Wih, Whh, bih, bhh);
    setup_graph<<<1, 1024>>>(conn, cw);
    setup_mm<<<65, 64>>>(W1, b1, W2);
    cudaFuncSetAttribute(gemm_kernel, cudaFuncAttributeMaxDynamicSharedMemorySize,
                         GEMM_SMEM_BYTES);
    gemm_kernel<<<TT, 256, GEMM_SMEM_BYTES>>>(b2, out);
    cudaFuncSetAttribute(gather_kernel, cudaFuncAttributeMaxDynamicSharedMemorySize,
                         GATH_SMEM_BYTES);
    gather_kernel<<<TT, 256, GATH_SMEM_BYTES>>>(out);
}

// round 5
// speedup vs baseline: 1.5557x; 1.1033x over previous
#include <cuda_runtime.h>

#define BB 16
#define LL 24
#define NN 256
#define EE 4096
#define HH 64
#define TT (BB*LL)      // 384 graphs
#define BN (BB*NN)      // 4096 LSTM samples
#define S_MAX 28        // samples per LSTM block (147 blocks, 1 wave)

// ---------------- packed f32x2 helpers ----------------
__device__ __forceinline__ unsigned long long packf2(float lo, float hi) {
    unsigned long long r;
    asm("mov.b64 %0,{%1,%2};" : "=l"(r) : "f"(lo), "f"(hi));
    return r;
}
__device__ __forceinline__ void unpackf2(unsigned long long v, float& lo, float& hi) {
    asm("mov.b64 {%0,%1},%2;" : "=f"(lo), "=f"(hi) : "l"(v));
}
__device__ __forceinline__ void ffma2(unsigned long long& d, unsigned long long a,
                                      unsigned long long b) {
    asm("fma.rn.f32x2 %0,%1,%2,%0;" : "+l"(d) : "l"(a), "l"(b));
}
__device__ __forceinline__ float tanha(float x) {
    float r; asm("tanh.approx.f32 %0,%1;" : "=f"(r) : "f"(x)); return r;
}
__device__ __forceinline__ float fsig(float x) { return 0.5f * tanha(0.5f * x) + 0.5f; }

// ---------------- device scratch ----------------
__device__ float g_Hout[TT * NN * HH];     // 25 MB
__device__ float g_V[TT * NN * HH];        // 25 MB
__device__ float g_M1[64 * 64];
__device__ float g_M2[64 * 64];
__device__ float g_Wc[64 * 64];
__device__ float g_G0[64], g_G1[64], g_Gb[64];
__device__ float g_s0v[NN], g_s1v[NN];
__device__ int   g_deg[NN];
__device__ int   g_off[NN + 1];
__device__ int   g_src[EE];

// ---------------- setup part 1: graph/CSR ----------------
__global__ void setup_graph(const int* __restrict__ conn,
                            const float* __restrict__ city_w)
{
    __shared__ float s0[NN], s1[NN];
    __shared__ int degs[NN], cur[NN], scan[NN];
    int t = threadIdx.x;

    if (t < NN) { s0[t] = 0.f; s1[t] = 0.f; degs[t] = 0; }
    __syncthreads();

    const int* row = conn;
    const int* col = conn + EE;
#pragma unroll
    for (int u = 0; u < EE / 1024; u++) {
        int e = u * 1024 + t;
        int c = col[e];
        atomicAdd(&degs[c], 1);
        atomicAdd(&s0[c], city_w[2 * e + 0]);
        atomicAdd(&s1[c], city_w[2 * e + 1]);
    }
    __syncthreads();

    if (t < NN) scan[t] = degs[t];
    __syncthreads();
    for (int d = 1; d < NN; d <<= 1) {
        int v = (t < NN && t >= d) ? scan[t - d] : 0;
        __syncthreads();
        if (t < NN) scan[t] += v;
        __syncthreads();
    }
    if (t < NN) {
        int excl = scan[t] - degs[t];
        g_off[t] = excl;
        cur[t] = excl;
        g_deg[t] = degs[t];
        g_s0v[t] = s0[t];
        g_s1v[t] = s1[t];
        if (t == NN - 1) g_off[NN] = scan[NN - 1];
    }
    __syncthreads();
#pragma unroll
    for (int u = 0; u < EE / 1024; u++) {
        int e = u * 1024 + t;
        int c = col[e];
        int p = atomicAdd(&cur[c], 1);
        g_src[p] = row[e];
    }
}

// ---------------- setup part 2: weight folds ----------------
__global__ void setup_mm(const float* __restrict__ W1,
                         const float* __restrict__ b1,
                         const float* __restrict__ W2)
{
    int c = threadIdx.x;
    int k = blockIdx.x;
    const float* W2b = W2 + 4096;
    if (k < 64) {
        __shared__ float w1a[64], w1b[64];
        if (c < 64) { w1a[c] = W1[k * 64 + c]; w1b[c] = W1[4096 + k * 64 + c]; }
        __syncthreads();
        float p0 = 0.f, p1 = 0.f, p2 = 0.f, p3 = 0.f;
        float q0 = 0.f, q1 = 0.f, q2 = 0.f, q3 = 0.f;
#pragma unroll
        for (int j = 0; j < 64; j += 4) {
            float v0 = W2b[(j + 0) * 64 + c];
            float v1 = W2b[(j + 1) * 64 + c];
            float v2 = W2b[(j + 2) * 64 + c];
            float v3 = W2b[(j + 3) * 64 + c];
            p0 += w1a[j + 0] * v0; q0 += w1b[j + 0] * v0;
            p1 += w1a[j + 1] * v1; q1 += w1b[j + 1] * v1;
            p2 += w1a[j + 2] * v2; q2 += w1b[j + 2] * v2;
            p3 += w1a[j + 3] * v3; q3 += w1b[j + 3] * v3;
        }
        float a1 = (p0 + p1) + (p2 + p3);
        float a2 = (q0 + q1) + (q2 + q3);
        g_M1[k * 64 + c] = a1;
        g_M2[k * 64 + c] = a2;
        g_Wc[k * 64 + c] = W2[k * 64 + c] + a2;
    } else {
        float a0 = 0.f, a1 = 0.f, ab = 0.f;
#pragma unroll 8
        for (int j = 0; j < 64; j++) {
            float w2 = W2b[j * 64 + c];
            a0 += W1[128 * 64 + j] * w2;
            a1 += W1[129 * 64 + j] * w2;
            ab += b1[j] * w2;
        }
        g_G0[c] = a0; g_G1[c] = a1; g_Gb[c] = ab;
    }
}

// ---------------- LSTM ----------------
__global__ void __launch_bounds__(256)
lstm_kernel(const float* __restrict__ aqi,
            const float* __restrict__ embW,
            const float* __restrict__ embB,
            const float* __restrict__ Wih,
            const float* __restrict__ Whh,
            const float* __restrict__ bih,
            const float* __restrict__ bhh)
{
    __shared__ __align__(16) float hS[S_MAX][64];
    __shared__ __align__(16) float cS[S_MAX][64];
    __shared__ __align__(16) float gS[S_MAX][256];
    __shared__ float aS[S_MAX][LL];

    int tid = threadIdx.x;
    int m0  = blockIdx.x * S_MAX;
    int cnt = BN - m0; if (cnt > S_MAX) cnt = S_MAX;

    unsigned long long w2[32];
    {
        const ulonglong2* wr = (const ulonglong2*)(Whh + tid * 64);
#pragma unroll
        for (int i = 0; i < 16; i++) {
            ulonglong2 v = wr[i];
            w2[2 * i] = v.x; w2[2 * i + 1] = v.y;
        }
    }
    float A = 0.f, Bc = 0.f;
#pragma unroll
    for (int j = 0; j < 16; j++) {
        float wi = Wih[tid * 16 + j];
        A  += wi * embW[j];
        Bc += wi * embB[j];
    }
    Bc += bih[tid] + bhh[tid];

    for (int idx = tid; idx < cnt * LL; idx += 256) {
        int s = idx / LL, l = idx % LL;
        int m = m0 + s; int b = m >> 8; int n = m & 255;
        aS[s][l] = aqi[(b * LL + l) * NN + n];
    }
    for (int idx = tid; idx < cnt * 64; idx += 256) {
        ((float*)hS)[idx] = 0.f; ((float*)cS)[idx] = 0.f;
    }
    __syncthreads();

    int j0 = (tid & 15) << 2;

    for (int l = 0; l < LL; l++) {
#pragma unroll 2
        for (int s = 0; s < cnt; s++) {
            unsigned long long a0 = 0ull, a1 = 0ull, a2 = 0ull, a3 = 0ull;
            const ulonglong2* hp = (const ulonglong2*)hS[s];
#pragma unroll
            for (int i = 0; i < 8; i++) {
                ulonglong2 h0 = hp[2 * i];
                ulonglong2 h1 = hp[2 * i + 1];
                ffma2(a0, h0.x, w2[4 * i + 0]);
                ffma2(a1, h0.y, w2[4 * i + 1]);
                ffma2(a2, h1.x, w2[4 * i + 2]);
                ffma2(a3, h1.y, w2[4 * i + 3]);
            }
            float l0, h0f, l1, h1f, l2, h2f, l3, h3f;
            unpackf2(a0, l0, h0f); unpackf2(a1, l1, h1f);
            unpackf2(a2, l2, h2f); unpackf2(a3, l3, h3f);
            gS[s][tid] = aS[s][l] * A + Bc +
                         (((l0 + h0f) + (l1 + h1f)) + ((l2 + h2f) + (l3 + h3f)));
        }
        __syncthreads();
        for (int sb = 0; sb < cnt; sb += 16) {
            int se = sb + (tid >> 4);
            if (se < cnt) {
                float4 gi = *(const float4*)&gS[se][j0];
                float4 gf = *(const float4*)&gS[se][64 + j0];
                float4 gg = *(const float4*)&gS[se][128 + j0];
                float4 go = *(const float4*)&gS[se][192 + j0];
                float4 c4 = *(const float4*)&cS[se][j0];
                c4.x = fsig(gf.x) * c4.x + fsig(gi.x) * tanha(gg.x);
                c4.y = fsig(gf.y) * c4.y + fsig(gi.y) * tanha(gg.y);
                c4.z = fsig(gf.z) * c4.z + fsig(gi.z) * tanha(gg.z);
                c4.w = fsig(gf.w) * c4.w + fsig(gi.w) * tanha(gg.w);
                float4 h4;
                h4.x = fsig(go.x) * tanha(c4.x);
                h4.y = fsig(go.y) * tanha(c4.y);
                h4.z = fsig(go.z) * tanha(c4.z);
                h4.w = fsig(go.w) * tanha(c4.w);
                *(float4*)&cS[se][j0] = c4;
                *(float4*)&hS[se][j0] = h4;
                int me = m0 + se; int be = me >> 8; int ne = me & 255;
                *(float4*)(g_Hout + ((size_t)(be * LL + l) * NN + ne) * 64 + j0) = h4;
            }
        }
        __syncthreads();
    }
}

// ---------------- GNN gemm: register-blocked 8x8 tiles ----------------
#define GEMM_SMEM_FLOATS (256 * 65 + 4096 + 4096 + 64)
#define GEMM_SMEM_BYTES  (GEMM_SMEM_FLOATS * 4)

__global__ void __launch_bounds__(256, 2)
gemm_kernel(const float* __restrict__ b2, float* __restrict__ out)
{
    extern __shared__ __align__(16) float sm[];
    float* Xs  = sm;                  // 256*65
    float* W1s = sm + 256 * 65;       // 4096 (M1)
    float* Wcs = W1s + 4096;          // 4096 (W2a + M2)
    float* b2s = Wcs + 4096;          // 64
    __shared__ int sdeg[NN];

    int tid = threadIdx.x;
    int t   = blockIdx.x;
    const float* Xg = g_Hout + (size_t)t * NN * 64;

    for (int idx = tid; idx < NN * 64; idx += 256)
        Xs[(idx >> 6) * 65 + (idx & 63)] = Xg[idx];
    for (int idx = tid; idx < 4096; idx += 256) {
        W1s[idx] = g_M1[idx];
        Wcs[idx] = g_Wc[idx];
    }
    if (tid < 64) b2s[tid] = b2[tid];
    sdeg[tid] = g_deg[tid];
    __syncthreads();

    int cg = tid & 7, ng = tid >> 3;
    int n0 = ng * 8, c0 = cg * 8;
    const float* xb = Xs + n0 * 65;

    unsigned long long acc[32];

    // ---- matmul 1: V = X @ M1 ----
#pragma unroll
    for (int i = 0; i < 32; i++) acc[i] = 0ull;
#pragma unroll 4
    for (int k = 0; k < 64; k++) {
        ulonglong2 wa = *(const ulonglong2*)(W1s + k * 64 + c0);
        ulonglong2 wb = *(const ulonglong2*)(W1s + k * 64 + c0 + 4);
#pragma unroll
        for (int n = 0; n < 8; n++) {
            float x = xb[n * 65 + k];
            unsigned long long xx = packf2(x, x);
            ffma2(acc[n * 4 + 0], xx, wa.x);
            ffma2(acc[n * 4 + 1], xx, wa.y);
            ffma2(acc[n * 4 + 2], xx, wb.x);
            ffma2(acc[n * 4 + 3], xx, wb.y);
        }
    }
    {
        float* vg = g_V + (size_t)t * NN * 64;
#pragma unroll
        for (int n = 0; n < 8; n++) {
            float4 v0, v1;
            unpackf2(acc[n * 4 + 0], v0.x, v0.y);
            unpackf2(acc[n * 4 + 1], v0.z, v0.w);
            unpackf2(acc[n * 4 + 2], v1.x, v1.y);
            unpackf2(acc[n * 4 + 3], v1.z, v1.w);
            float* p = vg + (n0 + n) * 64 + c0;
            *(float4*)p = v0;
            *(float4*)(p + 4) = v1;
        }
    }

    // ---- matmul 2: out = X @ Wc + b2 (deg==0: subtract X@M2) ----
#pragma unroll
    for (int i = 0; i < 32; i++) acc[i] = 0ull;
#pragma unroll 4
    for (int k = 0; k < 64; k++) {
        ulonglong2 wa = *(const ulonglong2*)(Wcs + k * 64 + c0);
        ulonglong2 wb = *(const ulonglong2*)(Wcs + k * 64 + c0 + 4);
#pragma unroll
        for (int n = 0; n < 8; n++) {
            float x = xb[n * 65 + k];
            unsigned long long xx = packf2(x, x);
            ffma2(acc[n * 4 + 0], xx, wa.x);
            ffma2(acc[n * 4 + 1], xx, wa.y);
            ffma2(acc[n * 4 + 2], xx, wb.x);
            ffma2(acc[n * 4 + 3], xx, wb.y);
        }
    }
    {
        float4 bb0 = *(const float4*)(b2s + c0);
        float4 bb1 = *(const float4*)(b2s + c0 + 4);
        float* og = out + (size_t)t * NN * 64;
#pragma unroll
        for (int n = 0; n < 8; n++) {
            float4 v0, v1;
            unpackf2(acc[n * 4 + 0], v0.x, v0.y);
            unpackf2(acc[n * 4 + 1], v0.z, v0.w);
            unpackf2(acc[n * 4 + 2], v1.x, v1.y);
            unpackf2(acc[n * 4 + 3], v1.z, v1.w);
            v0.x += bb0.x; v0.y += bb0.y; v0.z += bb0.z; v0.w += bb0.w;
            v1.x += bb1.x; v1.y += bb1.y; v1.z += bb1.z; v1.w += bb1.w;
            if (sdeg[n0 + n] == 0) {   // exact rare path
                float corr[8];
                for (int c = 0; c < 8; c++) {
                    float s = 0.f;
                    for (int k = 0; k < 64; k++)
                        s += xb[n * 65 + k] * g_M2[k * 64 + c0 + c];
                    corr[c] = s;
                }
                v0.x -= corr[0]; v0.y -= corr[1]; v0.z -= corr[2]; v0.w -= corr[3];
                v1.x -= corr[4]; v1.y -= corr[5]; v1.z -= corr[6]; v1.w -= corr[7];
            }
            float* p = og + (n0 + n) * 64 + c0;
            *(float4*)p = v0;
            *(float4*)(p + 4) = v1;
        }
    }
}

// ---------------- GNN gather: out += (sum_in V + Cp)/deg ----------------
#define GATH_SMEM_FLOATS (256 * 65 + 192)
#define GATH_SMEM_BYTES  (GATH_SMEM_FLOATS * 4)

__global__ void __launch_bounds__(256)
gather_kernel(float* __restrict__ out)
{
    extern __shared__ __align__(16) float sm[];
    float* Vs  = sm;
    float* G0s = sm + 256 * 65;
    float* G1s = G0s + 64;
    float* Gbs = G1s + 64;

    int tid = threadIdx.x;
    int t   = blockIdx.x;
    const float* Vg = g_V + (size_t)t * NN * 64;

    for (int idx = tid; idx < NN * 64; idx += 256)
        Vs[(idx >> 6) * 65 + (idx & 63)] = Vg[idx];
    if (tid < 64) { G0s[tid] = g_G0[tid]; G1s[tid] = g_G1[tid]; Gbs[tid] = g_Gb[tid]; }
    __syncthreads();

    int warp = tid >> 5, lane = tid & 31;
    for (int n = warp; n < NN; n += 8) {
        int lo = g_off[n], hi = g_off[n + 1];
        float a0 = 0.f, a1 = 0.f;
        int e = lo;
        for (; e + 4 <= hi; e += 4) {
            int i0 = g_src[e], i1 = g_src[e + 1], i2 = g_src[e + 2], i3 = g_src[e + 3];
            a0 += Vs[i0 * 65 + lane]      + Vs[i1 * 65 + lane]
                + Vs[i2 * 65 + lane]      + Vs[i3 * 65 + lane];
            a1 += Vs[i0 * 65 + 32 + lane] + Vs[i1 * 65 + 32 + lane]
                + Vs[i2 * 65 + 32 + lane] + Vs[i3 * 65 + 32 + lane];
        }
        for (; e < hi; e++) {
            int i0 = g_src[e];
            a0 += Vs[i0 * 65 + lane];
            a1 += Vs[i0 * 65 + 32 + lane];
        }
        float degf = (float)(hi - lo);
        float dinv = 1.f / fmaxf(degf, 1.f);
        float sn0 = g_s0v[n], sn1 = g_s1v[n];
        float cp0 = sn0 * G0s[lane]      + sn1 * G1s[lane]      + degf * Gbs[lane];
        float cp1 = sn0 * G0s[32 + lane] + sn1 * G1s[32 + lane] + degf * Gbs[32 + lane];
        float* op = out + ((size_t)t * NN + n) * 64;
        op[lane]      += (a0 + cp0) * dinv;
        op[32 + lane] += (a1 + cp1) * dinv;
    }
}

// ---------------- launch ----------------
extern "C" void kernel_launch(void* const* d_in, const int* in_sizes, int n_in,
                              void* d_out, int out_size)
{
    const float* aqi  = (const float*)d_in[0];
    const int*   conn = (const int*)  d_in[1];
    const float* cw   = (const float*)d_in[2];
    const float* embW = (const float*)d_in[3];
    const float* embB = (const float*)d_in[4];
    const float* Wih  = (const float*)d_in[5];
    const float* Whh  = (const float*)d_in[6];
    const float* bih  = (const float*)d_in[7];
    const float* bhh  = (const float*)d_in[8];
    const float* W1   = (const float*)d_in[9];
    const float* b1   = (const float*)d_in[10];
    const float* W2   = (const float*)d_in[11];
    const float* b2   = (const float*)d_in[12];
    float* out = (float*)d_out;

    int lstm_blocks = (BN + S_MAX - 1) / S_MAX;   // 147
    lstm_kernel<<<lstm_blocks, 256>>>(aqi, embW, embB, Wih, Whh, bih, bhh);
    setup_graph<<<1, 1024>>>(conn, cw);
    setup_mm<<<65, 64>>>(W1, b1, W2);
    cudaFuncSetAttribute(gemm_kernel, cudaFuncAttributeMaxDynamicSharedMemorySize,
                         GEMM_SMEM_BYTES);
    gemm_kernel<<<TT, 256, GEMM_SMEM_BYTES>>>(b2, out);
    cudaFuncSetAttribute(gather_kernel, cudaFuncAttributeMaxDynamicSharedMemorySize,
                         GATH_SMEM_BYTES);
    gather_kernel<<<TT, 256, GATH_SMEM_BYTES>>>(out);
}

// round 6
// speedup vs baseline: 1.9366x; 1.2448x over previous
#include <cuda_runtime.h>

#define BB 16
#define LL 24
#define NN 256
#define EE 4096
#define TT (BB*LL)      // 384 graphs
#define BN (BB*NN)      // 4096 LSTM samples
#define S_MAX 28        // samples per LSTM block (147 blocks)
#define PN 268          // padded node stride for transposed X (67 coprime 32)

// ---------------- packed f32x2 helpers ----------------
__device__ __forceinline__ unsigned long long packf2(float lo, float hi) {
    unsigned long long r;
    asm("mov.b64 %0,{%1,%2};" : "=l"(r) : "f"(lo), "f"(hi));
    return r;
}
__device__ __forceinline__ void unpackf2(unsigned long long v, float& lo, float& hi) {
    asm("mov.b64 {%0,%1},%2;" : "=f"(lo), "=f"(hi) : "l"(v));
}
__device__ __forceinline__ void ffma2(unsigned long long& d, unsigned long long a,
                                      unsigned long long b) {
    asm("fma.rn.f32x2 %0,%1,%2,%0;" : "+l"(d) : "l"(a), "l"(b));
}
__device__ __forceinline__ float tanha(float x) {
    float r; asm("tanh.approx.f32 %0,%1;" : "=f"(r) : "f"(x)); return r;
}
__device__ __forceinline__ float fsig(float x) { return 0.5f * tanha(0.5f * x) + 0.5f; }

// ---------------- device scratch ----------------
__device__ float g_Hout[TT * NN * 64];     // 25 MB
__device__ float g_M1[4096];
__device__ float g_M2[4096];
__device__ float g_Wc[4096];
__device__ float g_G0[64], g_G1[64], g_Gb[64];
__device__ float g_s0v[NN], g_s1v[NN];
__device__ int   g_deg[NN];
__device__ int   g_off[NN + 1];
__device__ int   g_src[EE];

// ---------------- setup part 1: graph/CSR ----------------
__global__ void setup_graph(const int* __restrict__ conn,
                            const float* __restrict__ city_w)
{
    __shared__ float s0[NN], s1[NN];
    __shared__ int degs[NN], cur[NN], scan[NN];
    int t = threadIdx.x;

    if (t < NN) { s0[t] = 0.f; s1[t] = 0.f; degs[t] = 0; }
    __syncthreads();

    const int* row = conn;
    const int* col = conn + EE;
#pragma unroll
    for (int u = 0; u < EE / 1024; u++) {
        int e = u * 1024 + t;
        int c = col[e];
        atomicAdd(&degs[c], 1);
        atomicAdd(&s0[c], city_w[2 * e + 0]);
        atomicAdd(&s1[c], city_w[2 * e + 1]);
    }
    __syncthreads();

    if (t < NN) scan[t] = degs[t];
    __syncthreads();
    for (int d = 1; d < NN; d <<= 1) {
        int v = (t < NN && t >= d) ? scan[t - d] : 0;
        __syncthreads();
        if (t < NN) scan[t] += v;
        __syncthreads();
    }
    if (t < NN) {
        int excl = scan[t] - degs[t];
        g_off[t] = excl;
        cur[t] = excl;
        g_deg[t] = degs[t];
        g_s0v[t] = s0[t];
        g_s1v[t] = s1[t];
        if (t == NN - 1) g_off[NN] = scan[NN - 1];
    }
    __syncthreads();
#pragma unroll
    for (int u = 0; u < EE / 1024; u++) {
        int e = u * 1024 + t;
        int c = col[e];
        int p = atomicAdd(&cur[c], 1);
        g_src[p] = row[e];
    }
}

// ---------------- setup part 2: weight folds ----------------
__global__ void setup_mm(const float* __restrict__ W1,
                         const float* __restrict__ b1,
                         const float* __restrict__ W2)
{
    int c = threadIdx.x;
    int k = blockIdx.x;
    const float* W2b = W2 + 4096;
    if (k < 64) {
        __shared__ float w1a[64], w1b[64];
        if (c < 64) { w1a[c] = W1[k * 64 + c]; w1b[c] = W1[4096 + k * 64 + c]; }
        __syncthreads();
        float p0 = 0.f, p1 = 0.f, p2 = 0.f, p3 = 0.f;
        float q0 = 0.f, q1 = 0.f, q2 = 0.f, q3 = 0.f;
#pragma unroll
        for (int j = 0; j < 64; j += 4) {
            float v0 = W2b[(j + 0) * 64 + c];
            float v1 = W2b[(j + 1) * 64 + c];
            float v2 = W2b[(j + 2) * 64 + c];
            float v3 = W2b[(j + 3) * 64 + c];
            p0 += w1a[j + 0] * v0; q0 += w1b[j + 0] * v0;
            p1 += w1a[j + 1] * v1; q1 += w1b[j + 1] * v1;
            p2 += w1a[j + 2] * v2; q2 += w1b[j + 2] * v2;
            p3 += w1a[j + 3] * v3; q3 += w1b[j + 3] * v3;
        }
        float a1 = (p0 + p1) + (p2 + p3);
        float a2 = (q0 + q1) + (q2 + q3);
        g_M1[k * 64 + c] = a1;
        g_M2[k * 64 + c] = a2;
        g_Wc[k * 64 + c] = W2[k * 64 + c] + a2;
    } else {
        float a0 = 0.f, a1 = 0.f, ab = 0.f;
#pragma unroll 8
        for (int j = 0; j < 64; j++) {
            float w2 = W2b[j * 64 + c];
            a0 += W1[128 * 64 + j] * w2;
            a1 += W1[129 * 64 + j] * w2;
            ab += b1[j] * w2;
        }
        g_G0[c] = a0; g_G1[c] = a1; g_Gb[c] = ab;
    }
}

// ---------------- LSTM: 512 threads, 2 sample-groups x 256 gate rows ----------------
__global__ void __launch_bounds__(512)
lstm_kernel(const float* __restrict__ aqi,
            const float* __restrict__ embW,
            const float* __restrict__ embB,
            const float* __restrict__ Wih,
            const float* __restrict__ Whh,
            const float* __restrict__ bih,
            const float* __restrict__ bhh)
{
    __shared__ __align__(16) float hS[S_MAX][64];
    __shared__ __align__(16) float cS[S_MAX][64];
    __shared__ __align__(16) float gS[S_MAX][256];
    __shared__ float aS[S_MAX][LL];

    int tid = threadIdx.x;
    int m0  = blockIdx.x * S_MAX;
    int cnt = BN - m0; if (cnt > S_MAX) cnt = S_MAX;

    int grp = tid >> 8;        // 0/1 sample-group
    int r   = tid & 255;       // gate row

    unsigned long long w2[32];
    {
        const ulonglong2* wr = (const ulonglong2*)(Whh + r * 64);
#pragma unroll
        for (int i = 0; i < 16; i++) {
            ulonglong2 v = wr[i];
            w2[2 * i] = v.x; w2[2 * i + 1] = v.y;
        }
    }
    float A = 0.f, Bc = 0.f;
#pragma unroll
    for (int j = 0; j < 16; j++) {
        float wi = Wih[r * 16 + j];
        A  += wi * embW[j];
        Bc += wi * embB[j];
    }
    Bc += bih[r] + bhh[r];

    for (int idx = tid; idx < cnt * LL; idx += 512) {
        int s = idx / LL, l = idx % LL;
        int m = m0 + s; int b = m >> 8; int n = m & 255;
        aS[s][l] = aqi[(b * LL + l) * NN + n];
    }
    for (int idx = tid; idx < cnt * 64; idx += 512) {
        ((float*)hS)[idx] = 0.f; ((float*)cS)[idx] = 0.f;
    }
    __syncthreads();

    int sbeg = grp * 14;
    int send = sbeg + 14; if (send > cnt) send = cnt;
    int se = tid >> 4;                 // 0..31 (>= cnt covers all)
    int j0 = (tid & 15) << 2;

    for (int l = 0; l < LL; l++) {
        for (int s = sbeg; s < send; s++) {
            unsigned long long a0 = 0ull, a1 = 0ull, a2 = 0ull, a3 = 0ull;
            const ulonglong2* hp = (const ulonglong2*)hS[s];
#pragma unroll
            for (int i = 0; i < 8; i++) {
                ulonglong2 h0 = hp[2 * i];
                ulonglong2 h1 = hp[2 * i + 1];
                ffma2(a0, h0.x, w2[4 * i + 0]);
                ffma2(a1, h0.y, w2[4 * i + 1]);
                ffma2(a2, h1.x, w2[4 * i + 2]);
                ffma2(a3, h1.y, w2[4 * i + 3]);
            }
            float l0, h0f, l1, h1f, l2, h2f, l3, h3f;
            unpackf2(a0, l0, h0f); unpackf2(a1, l1, h1f);
            unpackf2(a2, l2, h2f); unpackf2(a3, l3, h3f);
            gS[s][r] = aS[s][l] * A + Bc +
                       (((l0 + h0f) + (l1 + h1f)) + ((l2 + h2f) + (l3 + h3f)));
        }
        __syncthreads();
        if (se < cnt) {
            float4 gi = *(const float4*)&gS[se][j0];
            float4 gf = *(const float4*)&gS[se][64 + j0];
            float4 gg = *(const float4*)&gS[se][128 + j0];
            float4 go = *(const float4*)&gS[se][192 + j0];
            float4 c4 = *(const float4*)&cS[se][j0];
            c4.x = fsig(gf.x) * c4.x + fsig(gi.x) * tanha(gg.x);
            c4.y = fsig(gf.y) * c4.y + fsig(gi.y) * tanha(gg.y);
            c4.z = fsig(gf.z) * c4.z + fsig(gi.z) * tanha(gg.z);
            c4.w = fsig(gf.w) * c4.w + fsig(gi.w) * tanha(gg.w);
            float4 h4;
            h4.x = fsig(go.x) * tanha(c4.x);
            h4.y = fsig(go.y) * tanha(c4.y);
            h4.z = fsig(go.z) * tanha(c4.z);
            h4.w = fsig(go.w) * tanha(c4.w);
            *(float4*)&cS[se][j0] = c4;
            *(float4*)&hS[se][j0] = h4;
            int me = m0 + se; int be = me >> 8; int ne = me & 255;
            *(float4*)(g_Hout + ((size_t)(be * LL + l) * NN + ne) * 64 + j0) = h4;
        }
        __syncthreads();
    }
}

// ---------------- fused GNN: 128 persistent blocks x 3 graphs, 512 threads ----------------
#define FUSE_SMEM_FLOATS (64 * PN + 16384 + 4096 + 4096 + 64 + 192 + 512 + 4096 + 257 + 256)
#define FUSE_SMEM_BYTES  (FUSE_SMEM_FLOATS * 4)

__global__ void __launch_bounds__(512, 1)
gnn_fused(const float* __restrict__ b2, float* __restrict__ out)
{
    extern __shared__ __align__(16) float sm[];
    float* Xk  = sm;                       // 64*PN (transposed X; later aliased as Zbuf)
    float* Vs  = Xk + 64 * PN;             // 256*64
    float* W1s = Vs + 16384;               // 4096
    float* Wcs = W1s + 4096;               // 4096
    float* b2s = Wcs + 4096;               // 64
    float* G0s = b2s + 64;                 // 64
    float* G1s = G0s + 64;                 // 64
    float* Gbs = G1s + 64;                 // 64
    float* s0S = Gbs + 64;                 // 256
    float* s1S = s0S + 256;                // 256
    int* srcS  = (int*)(s1S + 256);        // 4096
    int* offS  = srcS + EE;                // 257
    int* degS  = offS + NN + 1;            // 256

    int tid = threadIdx.x;
    for (int i = tid; i < 4096; i += 512) {
        W1s[i] = g_M1[i];
        Wcs[i] = g_Wc[i];
        srcS[i] = g_src[i];
    }
    if (tid < 64) {
        b2s[tid] = b2[tid];
        G0s[tid] = g_G0[tid]; G1s[tid] = g_G1[tid]; Gbs[tid] = g_Gb[tid];
    }
    if (tid < 256) { s0S[tid] = g_s0v[tid]; s1S[tid] = g_s1v[tid]; degS[tid] = g_deg[tid]; }
    if (tid < 257) offS[tid] = g_off[tid];

    int cg = tid & 15, ng = tid >> 4;
    int c0 = cg * 4, n0 = ng * 8;
    int lane = tid & 31, warp = tid >> 5;

    for (int g = 0; g < 3; g++) {
        int t = blockIdx.x * 3 + g;
        const float* Xg = g_Hout + (size_t)t * NN * 64;
        for (int idx = tid; idx < NN * 64; idx += 512) {
            int n = idx >> 6, c = idx & 63;
            Xk[c * PN + n] = Xg[idx];
        }
        __syncthreads();   // X ready (also covers block constants on g==0)

        unsigned long long acc[16];

        // ---- mm1: V = X @ M1 ----
#pragma unroll
        for (int i = 0; i < 16; i++) acc[i] = 0ull;
#pragma unroll 4
        for (int k = 0; k < 64; k++) {
            float4 xa = *(const float4*)(Xk + k * PN + n0);
            float4 xb = *(const float4*)(Xk + k * PN + n0 + 4);
            ulonglong2 w = *(const ulonglong2*)(W1s + k * 64 + c0);
            unsigned long long x;
            x = packf2(xa.x, xa.x); ffma2(acc[0],  x, w.x); ffma2(acc[1],  x, w.y);
            x = packf2(xa.y, xa.y); ffma2(acc[2],  x, w.x); ffma2(acc[3],  x, w.y);
            x = packf2(xa.z, xa.z); ffma2(acc[4],  x, w.x); ffma2(acc[5],  x, w.y);
            x = packf2(xa.w, xa.w); ffma2(acc[6],  x, w.x); ffma2(acc[7],  x, w.y);
            x = packf2(xb.x, xb.x); ffma2(acc[8],  x, w.x); ffma2(acc[9],  x, w.y);
            x = packf2(xb.y, xb.y); ffma2(acc[10], x, w.x); ffma2(acc[11], x, w.y);
            x = packf2(xb.z, xb.z); ffma2(acc[12], x, w.x); ffma2(acc[13], x, w.y);
            x = packf2(xb.w, xb.w); ffma2(acc[14], x, w.x); ffma2(acc[15], x, w.y);
        }
#pragma unroll
        for (int n = 0; n < 8; n++) {
            float4 v;
            unpackf2(acc[2 * n], v.x, v.y);
            unpackf2(acc[2 * n + 1], v.z, v.w);
            *(float4*)(Vs + (n0 + n) * 64 + c0) = v;
        }

        // ---- mm2: Z = X @ Wc + b2 ----
#pragma unroll
        for (int i = 0; i < 16; i++) acc[i] = 0ull;
#pragma unroll 4
        for (int k = 0; k < 64; k++) {
            float4 xa = *(const float4*)(Xk + k * PN + n0);
            float4 xb = *(const float4*)(Xk + k * PN + n0 + 4);
            ulonglong2 w = *(const ulonglong2*)(Wcs + k * 64 + c0);
            unsigned long long x;
            x = packf2(xa.x, xa.x); ffma2(acc[0],  x, w.x); ffma2(acc[1],  x, w.y);
            x = packf2(xa.y, xa.y); ffma2(acc[2],  x, w.x); ffma2(acc[3],  x, w.y);
            x = packf2(xa.z, xa.z); ffma2(acc[4],  x, w.x); ffma2(acc[5],  x, w.y);
            x = packf2(xa.w, xa.w); ffma2(acc[6],  x, w.x); ffma2(acc[7],  x, w.y);
            x = packf2(xb.x, xb.x); ffma2(acc[8],  x, w.x); ffma2(acc[9],  x, w.y);
            x = packf2(xb.y, xb.y); ffma2(acc[10], x, w.x); ffma2(acc[11], x, w.y);
            x = packf2(xb.z, xb.z); ffma2(acc[12], x, w.x); ffma2(acc[13], x, w.y);
            x = packf2(xb.w, xb.w); ffma2(acc[14], x, w.x); ffma2(acc[15], x, w.y);
        }
        float4 bb = *(const float4*)(b2s + c0);
        float4 z[8];
#pragma unroll
        for (int n = 0; n < 8; n++) {
            unpackf2(acc[2 * n], z[n].x, z[n].y);
            unpackf2(acc[2 * n + 1], z[n].z, z[n].w);
            z[n].x += bb.x; z[n].y += bb.y; z[n].z += bb.z; z[n].w += bb.w;
            if (degS[n0 + n] == 0) {   // exact rare path: Z = X@W2a + b2
                float s0c = 0.f, s1c = 0.f, s2c = 0.f, s3c = 0.f;
                for (int k = 0; k < 64; k++) {
                    float xv = Xk[k * PN + n0 + n];
                    s0c += xv * g_M2[k * 64 + c0 + 0];
                    s1c += xv * g_M2[k * 64 + c0 + 1];
                    s2c += xv * g_M2[k * 64 + c0 + 2];
                    s3c += xv * g_M2[k * 64 + c0 + 3];
                }
                z[n].x -= s0c; z[n].y -= s1c; z[n].z -= s2c; z[n].w -= s3c;
            }
        }
        __syncthreads();   // all Xk reads done; Vs complete

        float* Zb = Xk;    // reuse X space for Z (node-major, stride 64)
#pragma unroll
        for (int n = 0; n < 8; n++)
            *(float4*)(Zb + (n0 + n) * 64 + c0) = z[n];
        __syncthreads();   // Zb ready

        // ---- gather: out = Z + (sum_in V + Cp)/deg ----
        for (int n = warp; n < NN; n += 16) {
            int lo = offS[n], hi = offS[n + 1];
            float a0 = 0.f, a1 = 0.f;
            int e = lo;
            for (; e + 4 <= hi; e += 4) {
                int i0 = srcS[e], i1 = srcS[e + 1], i2 = srcS[e + 2], i3 = srcS[e + 3];
                a0 += Vs[i0 * 64 + lane]      + Vs[i1 * 64 + lane]
                    + Vs[i2 * 64 + lane]      + Vs[i3 * 64 + lane];
                a1 += Vs[i0 * 64 + 32 + lane] + Vs[i1 * 64 + 32 + lane]
                    + Vs[i2 * 64 + 32 + lane] + Vs[i3 * 64 + 32 + lane];
            }
            for (; e < hi; e++) {
                int i0 = srcS[e];
                a0 += Vs[i0 * 64 + lane];
                a1 += Vs[i0 * 64 + 32 + lane];
            }
            float degf = (float)(hi - lo);
            float dinv = 1.f / fmaxf(degf, 1.f);
            float sn0 = s0S[n], sn1 = s1S[n];
            float cp0 = sn0 * G0s[lane]      + sn1 * G1s[lane]      + degf * Gbs[lane];
            float cp1 = sn0 * G0s[32 + lane] + sn1 * G1s[32 + lane] + degf * Gbs[32 + lane];
            float* op = out + ((size_t)t * NN + n) * 64;
            op[lane]      = Zb[n * 64 + lane]      + (a0 + cp0) * dinv;
            op[32 + lane] = Zb[n * 64 + 32 + lane] + (a1 + cp1) * dinv;
        }
        __syncthreads();   // protect Xk/Vs before next graph
    }
}

// ---------------- launch ----------------
extern "C" void kernel_launch(void* const* d_in, const int* in_sizes, int n_in,
                              void* d_out, int out_size)
{
    const float* aqi  = (const float*)d_in[0];
    const int*   conn = (const int*)  d_in[1];
    const float* cw   = (const float*)d_in[2];
    const float* embW = (const float*)d_in[3];
    const float* embB = (const float*)d_in[4];
    const float* Wih  = (const float*)d_in[5];
    const float* Whh  = (const float*)d_in[6];
    const float* bih  = (const float*)d_in[7];
    const float* bhh  = (const float*)d_in[8];
    const float* W1   = (const float*)d_in[9];
    const float* b1   = (const float*)d_in[10];
    const float* W2   = (const float*)d_in[11];
    const float* b2   = (const float*)d_in[12];
    float* out = (float*)d_out;

    setup_graph<<<1, 1024>>>(conn, cw);
    setup_mm<<<65, 64>>>(W1, b1, W2);
    int lstm_blocks = (BN + S_MAX - 1) / S_MAX;   // 147
    lstm_kernel<<<lstm_blocks, 512>>>(aqi, embW, embB, Wih, Whh, bih, bhh);
    cudaFuncSetAttribute(gnn_fused, cudaFuncAttributeMaxDynamicSharedMemorySize,
                         FUSE_SMEM_BYTES);
    gnn_fused<<<TT / 3, 512, FUSE_SMEM_BYTES>>>(b2, out);
}

// round 7
// speedup vs baseline: 1.9929x; 1.0291x over previous
#include <cuda_runtime.h>

#define BB 16
#define LL 24
#define NN 256
#define EE 4096
#define TT (BB*LL)      // 384 graphs
#define BN (BB*NN)      // 4096 LSTM samples
#define S_MAX 14        // samples per LSTM block (293 blocks, 2 blocks/SM)
#define PN 268          // padded node stride for transposed X (67 coprime 32)

// ---------------- packed f32x2 helpers ----------------
__device__ __forceinline__ unsigned long long packf2(float lo, float hi) {
    unsigned long long r;
    asm("mov.b64 %0,{%1,%2};" : "=l"(r) : "f"(lo), "f"(hi));
    return r;
}
__device__ __forceinline__ void unpackf2(unsigned long long v, float& lo, float& hi) {
    asm("mov.b64 {%0,%1},%2;" : "=f"(lo), "=f"(hi) : "l"(v));
}
__device__ __forceinline__ void ffma2(unsigned long long& d, unsigned long long a,
                                      unsigned long long b) {
    asm("fma.rn.f32x2 %0,%1,%2,%0;" : "+l"(d) : "l"(a), "l"(b));
}
__device__ __forceinline__ float tanha(float x) {
    float r; asm("tanh.approx.f32 %0,%1;" : "=f"(r) : "f"(x)); return r;
}
__device__ __forceinline__ float fsig(float x) { return 0.5f * tanha(0.5f * x) + 0.5f; }

// ---------------- device scratch ----------------
__device__ float g_Hout[TT * NN * 64];     // 25 MB
__device__ float g_M1[4096];
__device__ float g_M2[4096];
__device__ float g_Wc[4096];
__device__ float g_G0[64], g_G1[64], g_Gb[64];
__device__ float g_s0v[NN], g_s1v[NN];
__device__ int   g_deg[NN];
__device__ int   g_off[NN + 1];
__device__ int   g_src[EE];

// ---------------- setup part 1: graph/CSR ----------------
__global__ void setup_graph(const int* __restrict__ conn,
                            const float* __restrict__ city_w)
{
    __shared__ float s0[NN], s1[NN];
    __shared__ int degs[NN], cur[NN], scan[NN];
    int t = threadIdx.x;

    if (t < NN) { s0[t] = 0.f; s1[t] = 0.f; degs[t] = 0; }
    __syncthreads();

    const int* row = conn;
    const int* col = conn + EE;
#pragma unroll
    for (int u = 0; u < EE / 1024; u++) {
        int e = u * 1024 + t;
        int c = col[e];
        atomicAdd(&degs[c], 1);
        atomicAdd(&s0[c], city_w[2 * e + 0]);
        atomicAdd(&s1[c], city_w[2 * e + 1]);
    }
    __syncthreads();

    if (t < NN) scan[t] = degs[t];
    __syncthreads();
    for (int d = 1; d < NN; d <<= 1) {
        int v = (t < NN && t >= d) ? scan[t - d] : 0;
        __syncthreads();
        if (t < NN) scan[t] += v;
        __syncthreads();
    }
    if (t < NN) {
        int excl = scan[t] - degs[t];
        g_off[t] = excl;
        cur[t] = excl;
        g_deg[t] = degs[t];
        g_s0v[t] = s0[t];
        g_s1v[t] = s1[t];
        if (t == NN - 1) g_off[NN] = scan[NN - 1];
    }
    __syncthreads();
#pragma unroll
    for (int u = 0; u < EE / 1024; u++) {
        int e = u * 1024 + t;
        int c = col[e];
        int p = atomicAdd(&cur[c], 1);
        g_src[p] = row[e];
    }
}

// ---------------- setup part 2: weight folds ----------------
__global__ void setup_mm(const float* __restrict__ W1,
                         const float* __restrict__ b1,
                         const float* __restrict__ W2)
{
    int c = threadIdx.x;
    int k = blockIdx.x;
    const float* W2b = W2 + 4096;
    if (k < 64) {
        __shared__ float w1a[64], w1b[64];
        if (c < 64) { w1a[c] = W1[k * 64 + c]; w1b[c] = W1[4096 + k * 64 + c]; }
        __syncthreads();
        float p0 = 0.f, p1 = 0.f, p2 = 0.f, p3 = 0.f;
        float q0 = 0.f, q1 = 0.f, q2 = 0.f, q3 = 0.f;
#pragma unroll
        for (int j = 0; j < 64; j += 4) {
            float v0 = W2b[(j + 0) * 64 + c];
            float v1 = W2b[(j + 1) * 64 + c];
            float v2 = W2b[(j + 2) * 64 + c];
            float v3 = W2b[(j + 3) * 64 + c];
            p0 += w1a[j + 0] * v0; q0 += w1b[j + 0] * v0;
            p1 += w1a[j + 1] * v1; q1 += w1b[j + 1] * v1;
            p2 += w1a[j + 2] * v2; q2 += w1b[j + 2] * v2;
            p3 += w1a[j + 3] * v3; q3 += w1b[j + 3] * v3;
        }
        float a1 = (p0 + p1) + (p2 + p3);
        float a2 = (q0 + q1) + (q2 + q3);
        g_M1[k * 64 + c] = a1;
        g_M2[k * 64 + c] = a2;
        g_Wc[k * 64 + c] = W2[k * 64 + c] + a2;
    } else {
        float a0 = 0.f, a1 = 0.f, ab = 0.f;
#pragma unroll 8
        for (int j = 0; j < 64; j++) {
            float w2 = W2b[j * 64 + c];
            a0 += W1[128 * 64 + j] * w2;
            a1 += W1[129 * 64 + j] * w2;
            ab += b1[j] * w2;
        }
        g_G0[c] = a0; g_G1[c] = a1; g_Gb[c] = ab;
    }
}

// ---------------- LSTM: 256 threads, 14 samples, 2 blocks/SM ----------------
__global__ void __launch_bounds__(256, 2)
lstm_kernel(const float* __restrict__ aqi,
            const float* __restrict__ embW,
            const float* __restrict__ embB,
            const float* __restrict__ Wih,
            const float* __restrict__ Whh,
            const float* __restrict__ bih,
            const float* __restrict__ bhh)
{
    __shared__ __align__(16) float hS[S_MAX][64];
    __shared__ __align__(16) float cS[S_MAX][64];
    __shared__ __align__(16) float gS[S_MAX][256];
    __shared__ float aS[S_MAX][LL];

    int tid = threadIdx.x;          // gate row r
    int m0  = blockIdx.x * S_MAX;
    int cnt = BN - m0; if (cnt > S_MAX) cnt = S_MAX;

    unsigned long long w2[32];
    {
        const ulonglong2* wr = (const ulonglong2*)(Whh + tid * 64);
#pragma unroll
        for (int i = 0; i < 16; i++) {
            ulonglong2 v = wr[i];
            w2[2 * i] = v.x; w2[2 * i + 1] = v.y;
        }
    }
    float A = 0.f, Bc = 0.f;
#pragma unroll
    for (int j = 0; j < 16; j++) {
        float wi = Wih[tid * 16 + j];
        A  += wi * embW[j];
        Bc += wi * embB[j];
    }
    Bc += bih[tid] + bhh[tid];

    for (int idx = tid; idx < cnt * LL; idx += 256) {
        int s = idx / LL, l = idx % LL;
        int m = m0 + s; int b = m >> 8; int n = m & 255;
        aS[s][l] = aqi[(b * LL + l) * NN + n];
    }
    for (int idx = tid; idx < cnt * 64; idx += 256) {
        ((float*)hS)[idx] = 0.f; ((float*)cS)[idx] = 0.f;
    }
    __syncthreads();

    int se = tid >> 4;               // 0..15
    int j0 = (tid & 15) << 2;

    for (int l = 0; l < LL; l++) {
        for (int s = 0; s < cnt; s++) {
            unsigned long long a0 = 0ull, a1 = 0ull, a2 = 0ull, a3 = 0ull;
            const ulonglong2* hp = (const ulonglong2*)hS[s];
#pragma unroll
            for (int i = 0; i < 8; i++) {
                ulonglong2 h0 = hp[2 * i];
                ulonglong2 h1 = hp[2 * i + 1];
                ffma2(a0, h0.x, w2[4 * i + 0]);
                ffma2(a1, h0.y, w2[4 * i + 1]);
                ffma2(a2, h1.x, w2[4 * i + 2]);
                ffma2(a3, h1.y, w2[4 * i + 3]);
            }
            float l0, h0f, l1, h1f, l2, h2f, l3, h3f;
            unpackf2(a0, l0, h0f); unpackf2(a1, l1, h1f);
            unpackf2(a2, l2, h2f); unpackf2(a3, l3, h3f);
            gS[s][tid] = aS[s][l] * A + Bc +
                         (((l0 + h0f) + (l1 + h1f)) + ((l2 + h2f) + (l3 + h3f)));
        }
        __syncthreads();
        if (se < cnt) {
            float4 gi = *(const float4*)&gS[se][j0];
            float4 gf = *(const float4*)&gS[se][64 + j0];
            float4 gg = *(const float4*)&gS[se][128 + j0];
            float4 go = *(const float4*)&gS[se][192 + j0];
            float4 c4 = *(const float4*)&cS[se][j0];
            c4.x = fsig(gf.x) * c4.x + fsig(gi.x) * tanha(gg.x);
            c4.y = fsig(gf.y) * c4.y + fsig(gi.y) * tanha(gg.y);
            c4.z = fsig(gf.z) * c4.z + fsig(gi.z) * tanha(gg.z);
            c4.w = fsig(gf.w) * c4.w + fsig(gi.w) * tanha(gg.w);
            float4 h4;
            h4.x = fsig(go.x) * tanha(c4.x);
            h4.y = fsig(go.y) * tanha(c4.y);
            h4.z = fsig(go.z) * tanha(c4.z);
            h4.w = fsig(go.w) * tanha(c4.w);
            *(float4*)&cS[se][j0] = c4;
            *(float4*)&hS[se][j0] = h4;
            int me = m0 + se; int be = me >> 8; int ne = me & 255;
            *(float4*)(g_Hout + ((size_t)(be * LL + l) * NN + ne) * 64 + j0) = h4;
        }
        __syncthreads();
    }
}

// ---------------- fused GNN: 128 blocks x 3 graphs, 512 threads ----------------
#define FUSE_SMEM_FLOATS (64 * PN + 16384 + 4096 + 4096 + 64 + 192 + 512 + 4096 + 257 + 256)
#define FUSE_SMEM_BYTES  (FUSE_SMEM_FLOATS * 4)

__global__ void __launch_bounds__(512, 1)
gnn_fused(const float* __restrict__ b2, float* __restrict__ out)
{
    extern __shared__ __align__(16) float sm[];
    float* Xk  = sm;                       // 64*PN (transposed X; aliased as Zbuf later)
    float* Vs  = Xk + 64 * PN;             // 256*64
    float* W1s = Vs + 16384;               // 4096
    float* Wcs = W1s + 4096;               // 4096
    float* b2s = Wcs + 4096;               // 64
    float* G0s = b2s + 64;                 // 64
    float* G1s = G0s + 64;                 // 64
    float* Gbs = G1s + 64;                 // 64
    float* s0S = Gbs + 64;                 // 256
    float* s1S = s0S + 256;                // 256
    int* srcS  = (int*)(s1S + 256);        // 4096
    int* offS  = srcS + EE;                // 257
    int* degS  = offS + NN + 1;            // 256

    int tid = threadIdx.x;
    for (int i = tid; i < 4096; i += 512) {
        W1s[i] = g_M1[i];
        Wcs[i] = g_Wc[i];
        srcS[i] = g_src[i];
    }
    if (tid < 64) {
        b2s[tid] = b2[tid];
        G0s[tid] = g_G0[tid]; G1s[tid] = g_G1[tid]; Gbs[tid] = g_Gb[tid];
    }
    if (tid < 256) { s0S[tid] = g_s0v[tid]; s1S[tid] = g_s1v[tid]; degS[tid] = g_deg[tid]; }
    if (tid < 257) offS[tid] = g_off[tid];

    int cg = tid & 15, ng = tid >> 4;
    int c0 = cg * 4, n0 = ng * 8;
    int lane = tid & 31, warp = tid >> 5;

    for (int g = 0; g < 3; g++) {
        int t = blockIdx.x * 3 + g;
        const float* Xg = g_Hout + (size_t)t * NN * 64;
        for (int idx = tid; idx < NN * 64; idx += 512) {
            int n = idx >> 6, c = idx & 63;
            Xk[c * PN + n] = Xg[idx];
        }
        __syncthreads();   // X ready

        unsigned long long acc1[16], acc2[16];
#pragma unroll
        for (int i = 0; i < 16; i++) { acc1[i] = 0ull; acc2[i] = 0ull; }

        // ---- fused mm1 (V = X@M1) + mm2 (Z = X@Wc) : X read once ----
#pragma unroll 4
        for (int k = 0; k < 64; k++) {
            float4 xa = *(const float4*)(Xk + k * PN + n0);
            float4 xb = *(const float4*)(Xk + k * PN + n0 + 4);
            ulonglong2 w1 = *(const ulonglong2*)(W1s + k * 64 + c0);
            ulonglong2 wc = *(const ulonglong2*)(Wcs + k * 64 + c0);
            unsigned long long x;
            x = packf2(xa.x, xa.x);
            ffma2(acc1[0],  x, w1.x); ffma2(acc1[1],  x, w1.y);
            ffma2(acc2[0],  x, wc.x); ffma2(acc2[1],  x, wc.y);
            x = packf2(xa.y, xa.y);
            ffma2(acc1[2],  x, w1.x); ffma2(acc1[3],  x, w1.y);
            ffma2(acc2[2],  x, wc.x); ffma2(acc2[3],  x, wc.y);
            x = packf2(xa.z, xa.z);
            ffma2(acc1[4],  x, w1.x); ffma2(acc1[5],  x, w1.y);
            ffma2(acc2[4],  x, wc.x); ffma2(acc2[5],  x, wc.y);
            x = packf2(xa.w, xa.w);
            ffma2(acc1[6],  x, w1.x); ffma2(acc1[7],  x, w1.y);
            ffma2(acc2[6],  x, wc.x); ffma2(acc2[7],  x, wc.y);
            x = packf2(xb.x, xb.x);
            ffma2(acc1[8],  x, w1.x); ffma2(acc1[9],  x, w1.y);
            ffma2(acc2[8],  x, wc.x); ffma2(acc2[9],  x, wc.y);
            x = packf2(xb.y, xb.y);
            ffma2(acc1[10], x, w1.x); ffma2(acc1[11], x, w1.y);
            ffma2(acc2[10], x, wc.x); ffma2(acc2[11], x, wc.y);
            x = packf2(xb.z, xb.z);
            ffma2(acc1[12], x, w1.x); ffma2(acc1[13], x, w1.y);
            ffma2(acc2[12], x, wc.x); ffma2(acc2[13], x, wc.y);
            x = packf2(xb.w, xb.w);
            ffma2(acc1[14], x, w1.x); ffma2(acc1[15], x, w1.y);
            ffma2(acc2[14], x, wc.x); ffma2(acc2[15], x, wc.y);
        }

        // V -> Vs
#pragma unroll
        for (int n = 0; n < 8; n++) {
            float4 v;
            unpackf2(acc1[2 * n], v.x, v.y);
            unpackf2(acc1[2 * n + 1], v.z, v.w);
            *(float4*)(Vs + (n0 + n) * 64 + c0) = v;
        }

        // Z = acc2 + b2 (deg==0 rare path: subtract X@M2)
        float4 bb = *(const float4*)(b2s + c0);
        float4 z[8];
#pragma unroll
        for (int n = 0; n < 8; n++) {
            unpackf2(acc2[2 * n], z[n].x, z[n].y);
            unpackf2(acc2[2 * n + 1], z[n].z, z[n].w);
            z[n].x += bb.x; z[n].y += bb.y; z[n].z += bb.z; z[n].w += bb.w;
            if (degS[n0 + n] == 0) {
                float s0c = 0.f, s1c = 0.f, s2c = 0.f, s3c = 0.f;
                for (int k = 0; k < 64; k++) {
                    float xv = Xk[k * PN + n0 + n];
                    s0c += xv * g_M2[k * 64 + c0 + 0];
                    s1c += xv * g_M2[k * 64 + c0 + 1];
                    s2c += xv * g_M2[k * 64 + c0 + 2];
                    s3c += xv * g_M2[k * 64 + c0 + 3];
                }
                z[n].x -= s0c; z[n].y -= s1c; z[n].z -= s2c; z[n].w -= s3c;
            }
        }
        __syncthreads();   // all Xk reads done; Vs complete

        float* Zb = Xk;    // reuse X space for Z (node-major, stride 64)
#pragma unroll
        for (int n = 0; n < 8; n++)
            *(float4*)(Zb + (n0 + n) * 64 + c0) = z[n];
        __syncthreads();   // Zb ready

        // ---- gather: out = Z + (sum_in V + Cp)/deg ----
        for (int n = warp; n < NN; n += 16) {
            int lo = offS[n], hi = offS[n + 1];
            float a0 = 0.f, a1 = 0.f;
            int e = lo;
            for (; e + 4 <= hi; e += 4) {
                int i0 = srcS[e], i1 = srcS[e + 1], i2 = srcS[e + 2], i3 = srcS[e + 3];
                a0 += Vs[i0 * 64 + lane]      + Vs[i1 * 64 + lane]
                    + Vs[i2 * 64 + lane]      + Vs[i3 * 64 + lane];
                a1 += Vs[i0 * 64 + 32 + lane] + Vs[i1 * 64 + 32 + lane]
                    + Vs[i2 * 64 + 32 + lane] + Vs[i3 * 64 + 32 + lane];
            }
            for (; e < hi; e++) {
                int i0 = srcS[e];
                a0 += Vs[i0 * 64 + lane];
                a1 += Vs[i0 * 64 + 32 + lane];
            }
            float degf = (float)(hi - lo);
            float dinv = 1.f / fmaxf(degf, 1.f);
            float sn0 = s0S[n], sn1 = s1S[n];
            float cp0 = sn0 * G0s[lane]      + sn1 * G1s[lane]      + degf * Gbs[lane];
            float cp1 = sn0 * G0s[32 + lane] + sn1 * G1s[32 + lane] + degf * Gbs[32 + lane];
            float* op = out + ((size_t)t * NN + n) * 64;
            op[lane]      = Zb[n * 64 + lane]      + (a0 + cp0) * dinv;
            op[32 + lane] = Zb[n * 64 + 32 + lane] + (a1 + cp1) * dinv;
        }
        __syncthreads();   // protect Xk/Vs before next graph
    }
}

// ---------------- launch ----------------
extern "C" void kernel_launch(void* const* d_in, const int* in_sizes, int n_in,
                              void* d_out, int out_size)
{
    const float* aqi  = (const float*)d_in[0];
    const int*   conn = (const int*)  d_in[1];
    const float* cw   = (const float*)d_in[2];
    const float* embW = (const float*)d_in[3];
    const float* embB = (const float*)d_in[4];
    const float* Wih  = (const float*)d_in[5];
    const float* Whh  = (const float*)d_in[6];
    const float* bih  = (const float*)d_in[7];
    const float* bhh  = (const float*)d_in[8];
    const float* W1   = (const float*)d_in[9];
    const float* b1   = (const float*)d_in[10];
    const float* W2   = (const float*)d_in[11];
    const float* b2   = (const float*)d_in[12];
    float* out = (float*)d_out;

    setup_graph<<<1, 1024>>>(conn, cw);
    setup_mm<<<65, 64>>>(W1, b1, W2);
    int lstm_blocks = (BN + S_MAX - 1) / S_MAX;   // 293
    lstm_kernel<<<lstm_blocks, 256>>>(aqi, embW, embB, Wih, Whh, bih, bhh);
    cudaFuncSetAttribute(gnn_fused, cudaFuncAttributeMaxDynamicSharedMemorySize,
                         FUSE_SMEM_BYTES);
    gnn_fused<<<TT / 3, 512, FUSE_SMEM_BYTES>>>(b2, out);
}